// round 1
// baseline (speedup 1.0000x reference)
#include <cuda_runtime.h>
#include <math.h>

#define NB   4
#define NT   1024
#define ND   512
#define NH   8
#define NHD  64
#define NM   (NB*NT)     // 4096 rows

// ------------------- scratch (device globals; no allocs allowed) ----------
__device__ float g_Q[NM*ND];
__device__ float g_K[NM*ND];
__device__ float g_V[NM*ND];
__device__ float g_ctx[NM*ND];
__device__ float g_proj[NM*ND];

// ===========================================================================
// GEMM: out[m,n] = sum_k A[m,k]*W[n,k] + bias[n]   (M=4096, N=512, K=512)
// 128x128 block, ktile=16, 256 threads (16x16), 8x8 per thread.
// ===========================================================================
__device__ __forceinline__ void gemm_nt_128(const float* __restrict__ A,
                                            const float* __restrict__ W,
                                            const float* __restrict__ bias,
                                            float* __restrict__ out)
{
    __shared__ float As[128][17];
    __shared__ float Bs[128][17];
    const int tx = threadIdx.x, ty = threadIdx.y;
    const int tid = ty*16 + tx;
    const int row0 = blockIdx.y * 128;
    const int col0 = blockIdx.x * 128;

    float acc[8][8];
#pragma unroll
    for (int i=0;i<8;i++)
#pragma unroll
        for (int j=0;j<8;j++) acc[i][j] = 0.f;

    for (int kt = 0; kt < ND; kt += 16) {
#pragma unroll
        for (int u=0; u<2; u++) {
            int c  = tid + u*256;
            int r  = c >> 2;
            int kq = (c & 3) << 2;
            float4 a = *(const float4*)(A + (size_t)(row0+r)*ND + kt + kq);
            As[r][kq+0]=a.x; As[r][kq+1]=a.y; As[r][kq+2]=a.z; As[r][kq+3]=a.w;
            float4 b = *(const float4*)(W + (size_t)(col0+r)*ND + kt + kq);
            Bs[r][kq+0]=b.x; Bs[r][kq+1]=b.y; Bs[r][kq+2]=b.z; Bs[r][kq+3]=b.w;
        }
        __syncthreads();
#pragma unroll
        for (int kk=0; kk<16; kk++) {
            float a[8], bb[8];
#pragma unroll
            for (int i=0;i<4;i++) {
                a[i]    = As[ty*4+i][kk];
                a[4+i]  = As[64+ty*4+i][kk];
                bb[i]   = Bs[tx*4+i][kk];
                bb[4+i] = Bs[64+tx*4+i][kk];
            }
#pragma unroll
            for (int i=0;i<8;i++)
#pragma unroll
                for (int j=0;j<8;j++) acc[i][j] += a[i]*bb[j];
        }
        __syncthreads();
    }

    // epilogue: vectorized float4 stores, bias added
#pragma unroll
    for (int i=0;i<8;i++) {
        int r  = row0 + ((i<4) ? (ty*4+i) : (64 + ty*4 + (i-4)));
        int c0 = col0 + tx*4;
        int c1 = col0 + 64 + tx*4;
        float4 o0, o1;
        o0.x = acc[i][0] + bias[c0+0];
        o0.y = acc[i][1] + bias[c0+1];
        o0.z = acc[i][2] + bias[c0+2];
        o0.w = acc[i][3] + bias[c0+3];
        o1.x = acc[i][4] + bias[c1+0];
        o1.y = acc[i][5] + bias[c1+1];
        o1.z = acc[i][6] + bias[c1+2];
        o1.w = acc[i][7] + bias[c1+3];
        *(float4*)(out + (size_t)r*ND + c0) = o0;
        *(float4*)(out + (size_t)r*ND + c1) = o1;
    }
}

__global__ void __launch_bounds__(256,1)
k_qkv(const float* __restrict__ q, const float* __restrict__ k, const float* __restrict__ v,
      const float* __restrict__ Wq, const float* __restrict__ bq,
      const float* __restrict__ Wk, const float* __restrict__ bk,
      const float* __restrict__ Wv, const float* __restrict__ bv)
{
    if      (blockIdx.z == 0) gemm_nt_128(q, Wq, bq, g_Q);
    else if (blockIdx.z == 1) gemm_nt_128(k, Wk, bk, g_K);
    else                      gemm_nt_128(v, Wv, bv, g_V);
}

__global__ void __launch_bounds__(256,1)
k_oproj(const float* __restrict__ Wo, const float* __restrict__ bo)
{
    gemm_nt_128(g_ctx, Wo, bo, g_proj);
}

// ===========================================================================
// Flash attention with transport bias.
// CTA = (b, h, 128-query tile). 256 threads (16x16).
//   S tile: 128q x 128kv, thread = 8 rows x 8 cols
//   PV:     out 128q x 64d, thread = 8 rows x 4 cols
// scale folded into Q at load; bias = log(guide+1e-8)*softplus(bias_scale).
// ===========================================================================
#define QS_S 67
#define KS_S 67
#define VS_S 68
#define PS_S 129
#define SMEM_ATTN ((128*QS_S + 128*KS_S + 128*VS_S + 128*PS_S)*4)

__global__ void __launch_bounds__(256,1)
k_attn(const float* __restrict__ guide, const float* __restrict__ bias_scale)
{
    extern __shared__ float sm[];
    float* Qs = sm;                       // [128][67]  (q rows x d), scale folded
    float* Ks = Qs + 128*QS_S;            // [128][67]  (kv rows x d)
    float* Vs = Ks + 128*KS_S;            // [128][68]  (kv rows x d)
    float* Ps = Vs + 128*VS_S;            // [128][129] (q rows x kv)

    const int tx = threadIdx.x, ty = threadIdx.y;
    const int tid = ty*16 + tx;
    const int q0 = blockIdx.x * 128;
    const int b  = blockIdx.y >> 3;
    const int h  = blockIdx.y & 7;

    const float bs = bias_scale[0];
    const float sp = (bs > 20.f) ? bs : log1pf(__expf(bs));
    const float scale = 0.125f;           // 64^-0.5

    int R[8], C[8];
#pragma unroll
    for (int i=0;i<4;i++) {
        R[i]   = ty*4 + i;   R[4+i] = 64 + ty*4 + i;
        C[i]   = tx*4 + i;   C[4+i] = 64 + tx*4 + i;
    }

    // load Q tile (scale folded)
#pragma unroll
    for (int u=0; u<8; u++) {
        int c  = tid + u*256;
        int r  = c >> 4;
        int dq = (c & 15) << 2;
        float4 x = *(const float4*)(g_Q + (size_t)(b*NT + q0 + r)*ND + h*NHD + dq);
        Qs[r*QS_S + dq+0] = x.x*scale;
        Qs[r*QS_S + dq+1] = x.y*scale;
        Qs[r*QS_S + dq+2] = x.z*scale;
        Qs[r*QS_S + dq+3] = x.w*scale;
    }

    float m[8], l[8], acc[8][4];
#pragma unroll
    for (int i=0;i<8;i++) {
        m[i] = -1e30f; l[i] = 0.f;
#pragma unroll
        for (int j=0;j<4;j++) acc[i][j] = 0.f;
    }

    for (int t = 0; t < NT; t += 128) {
        __syncthreads();   // prior iter done reading Ks/Vs/Ps
        // load K,V tiles
#pragma unroll
        for (int u=0; u<8; u++) {
            int c  = tid + u*256;
            int r  = c >> 4;
            int dq = (c & 15) << 2;
            size_t goff = (size_t)(b*NT + t + r)*ND + h*NHD + dq;
            float4 kx = *(const float4*)(g_K + goff);
            Ks[r*KS_S + dq+0]=kx.x; Ks[r*KS_S + dq+1]=kx.y;
            Ks[r*KS_S + dq+2]=kx.z; Ks[r*KS_S + dq+3]=kx.w;
            float4 vx = *(const float4*)(g_V + goff);
            *(float4*)(Vs + r*VS_S + dq) = vx;
        }
        __syncthreads();

        // S = Q K^T (scale pre-folded)
        float s[8][8];
#pragma unroll
        for (int i=0;i<8;i++)
#pragma unroll
            for (int j=0;j<8;j++) s[i][j] = 0.f;

#pragma unroll 8
        for (int dd=0; dd<64; dd++) {
            float a[8], bb[8];
#pragma unroll
            for (int i=0;i<8;i++) { a[i]=Qs[R[i]*QS_S+dd]; bb[i]=Ks[C[i]*KS_S+dd]; }
#pragma unroll
            for (int i=0;i<8;i++)
#pragma unroll
                for (int j=0;j<8;j++) s[i][j] += a[i]*bb[j];
        }

        // + transport bias (vectorized gmem loads; L2-resident guide)
#pragma unroll
        for (int i=0;i<8;i++) {
            size_t gr = (size_t)(b*NT + q0 + R[i])*NT + t;
            float4 g0 = *(const float4*)(guide + gr + tx*4);
            float4 g1 = *(const float4*)(guide + gr + 64 + tx*4);
            s[i][0] += __logf(g0.x + 1e-8f)*sp;
            s[i][1] += __logf(g0.y + 1e-8f)*sp;
            s[i][2] += __logf(g0.z + 1e-8f)*sp;
            s[i][3] += __logf(g0.w + 1e-8f)*sp;
            s[i][4] += __logf(g1.x + 1e-8f)*sp;
            s[i][5] += __logf(g1.y + 1e-8f)*sp;
            s[i][6] += __logf(g1.z + 1e-8f)*sp;
            s[i][7] += __logf(g1.w + 1e-8f)*sp;
        }

        // online softmax per q-row (row spread across the 16 tx lanes)
#pragma unroll
        for (int i=0;i<8;i++) {
            float mx = s[i][0];
#pragma unroll
            for (int j=1;j<8;j++) mx = fmaxf(mx, s[i][j]);
#pragma unroll
            for (int o=8;o>=1;o>>=1) mx = fmaxf(mx, __shfl_xor_sync(0xffffffffu, mx, o));
            float mnew = fmaxf(m[i], mx);
            float corr = __expf(m[i] - mnew);
            m[i] = mnew;
            float rs = 0.f;
#pragma unroll
            for (int j=0;j<8;j++) {
                float p = __expf(s[i][j] - mnew);
                Ps[R[i]*PS_S + C[j]] = p;
                rs += p;
            }
#pragma unroll
            for (int o=8;o>=1;o>>=1) rs += __shfl_xor_sync(0xffffffffu, rs, o);
            l[i] = l[i]*corr + rs;
#pragma unroll
            for (int j=0;j<4;j++) acc[i][j] *= corr;
        }
        __syncthreads();   // Ps visible to all

        // acc += P @ V
#pragma unroll 4
        for (int kk=0; kk<128; kk++) {
            float4 vv = *(const float4*)(Vs + kk*VS_S + tx*4);
#pragma unroll
            for (int i=0;i<8;i++) {
                float p = Ps[R[i]*PS_S + kk];
                acc[i][0] += p*vv.x;
                acc[i][1] += p*vv.y;
                acc[i][2] += p*vv.z;
                acc[i][3] += p*vv.w;
            }
        }
    }

    // normalize + write context [B*T, D] at head slice
#pragma unroll
    for (int i=0;i<8;i++) {
        float inv = 1.f / l[i];
        float4 o;
        o.x = acc[i][0]*inv; o.y = acc[i][1]*inv;
        o.z = acc[i][2]*inv; o.w = acc[i][3]*inv;
        *(float4*)(g_ctx + (size_t)(b*NT + q0 + R[i])*ND + h*NHD + tx*4) = o;
    }
}

// ===========================================================================
// Fused residual + gate + LayerNorm.  One 128-thread block per row.
// ===========================================================================
__global__ void __launch_bounds__(128,8)
k_ln(const float* __restrict__ qin, const float* __restrict__ gate,
     const float* __restrict__ gamma, const float* __restrict__ beta,
     float* __restrict__ out)
{
    const int row = blockIdx.x;
    const int t   = threadIdx.x;
    const int wid = t >> 5, lane = t & 31;
    const float sg = 1.f/(1.f + __expf(-gate[0]));

    float y[4];
    float s = 0.f;
#pragma unroll
    for (int u=0;u<4;u++) {
        int c = t + u*128;
        y[u] = qin[(size_t)row*ND + c] + sg * g_proj[(size_t)row*ND + c];
        s += y[u];
    }
    __shared__ float red1[4], red2[4];
#pragma unroll
    for (int o=16;o>=1;o>>=1) s += __shfl_xor_sync(0xffffffffu, s, o);
    if (lane==0) red1[wid] = s;
    __syncthreads();
    float mu = (red1[0]+red1[1]+red1[2]+red1[3]) * (1.f/ND);

    float vs = 0.f;
#pragma unroll
    for (int u=0;u<4;u++) { float d = y[u]-mu; vs += d*d; }
#pragma unroll
    for (int o=16;o>=1;o>>=1) vs += __shfl_xor_sync(0xffffffffu, vs, o);
    if (lane==0) red2[wid] = vs;
    __syncthreads();
    float var  = (red2[0]+red2[1]+red2[2]+red2[3]) * (1.f/ND);
    float rstd = rsqrtf(var + 1e-5f);

#pragma unroll
    for (int u=0;u<4;u++) {
        int c = t + u*128;
        out[(size_t)row*ND + c] = (y[u]-mu)*rstd*gamma[c] + beta[c];
    }
}

// ===========================================================================
extern "C" void kernel_launch(void* const* d_in, const int* in_sizes, int n_in,
                              void* d_out, int out_size)
{
    (void)in_sizes; (void)n_in; (void)out_size;
    const float* q          = (const float*)d_in[0];
    const float* k          = (const float*)d_in[1];
    const float* v          = (const float*)d_in[2];
    const float* guide      = (const float*)d_in[3];
    const float* Wq         = (const float*)d_in[4];
    const float* bq         = (const float*)d_in[5];
    const float* Wk         = (const float*)d_in[6];
    const float* bk         = (const float*)d_in[7];
    const float* Wv         = (const float*)d_in[8];
    const float* bv         = (const float*)d_in[9];
    const float* Wo         = (const float*)d_in[10];
    const float* bo         = (const float*)d_in[11];
    const float* ln_gamma   = (const float*)d_in[12];
    const float* ln_beta    = (const float*)d_in[13];
    const float* gate       = (const float*)d_in[14];
    const float* bias_scale = (const float*)d_in[15];
    float* out = (float*)d_out;

    cudaFuncSetAttribute(k_attn, cudaFuncAttributeMaxDynamicSharedMemorySize, SMEM_ATTN);

    dim3 blk(16,16);
    // Q/K/V projections (fused across gridDim.z)
    k_qkv<<<dim3(ND/128, NM/128, 3), blk>>>(q, k, v, Wq, bq, Wk, bk, Wv, bv);
    // attention
    k_attn<<<dim3(NT/128, NB*NH), blk, SMEM_ATTN>>>(guide, bias_scale);
    // output projection
    k_oproj<<<dim3(ND/128, NM/128), blk>>>(Wo, bo);
    // residual + gate + layernorm
    k_ln<<<NM, 128>>>(q, gate, ln_gamma, ln_beta, out);
}

// round 2
// speedup vs baseline: 2.4952x; 2.4952x over previous
#include <cuda_runtime.h>
#include <math.h>

#define NB   4
#define NT   1024
#define ND   512
#define NH   8
#define NHD  64
#define NM   (NB*NT)     // 4096 rows

// ------------------- scratch (device globals; no allocs allowed) ----------
__device__ float g_Q[NM*ND];
__device__ float g_K[NM*ND];
__device__ float g_V[NM*ND];
__device__ float g_ctx[NM*ND];
__device__ float g_proj[NM*ND];

// ------------------- tf32 helpers -----------------------------------------
__device__ __forceinline__ unsigned f2tf(float f) {
    unsigned r;
    asm("cvt.rna.tf32.f32 %0, %1;" : "=r"(r) : "f"(f));
    return r;
}
__device__ __forceinline__ void mma8(float* c, unsigned a0, unsigned a1,
                                     unsigned a2, unsigned a3,
                                     unsigned b0, unsigned b1) {
    asm volatile(
        "mma.sync.aligned.m16n8k8.row.col.f32.tf32.tf32.f32 "
        "{%0,%1,%2,%3},{%4,%5,%6,%7},{%8,%9},{%0,%1,%2,%3};\n"
        : "+f"(c[0]), "+f"(c[1]), "+f"(c[2]), "+f"(c[3])
        : "r"(a0), "r"(a1), "r"(a2), "r"(a3), "r"(b0), "r"(b1));
}

// ===========================================================================
// tf32 GEMM: out[m,n] = sum_k A[m,k]*W[n,k] + bias[n]  (M=4096,N=512,K=512)
// CTA 128x128, 256 thr = 8 warps (4 along M x 2 along N), warp tile 32x64.
// ktile = 32. Smem stride 36 (== 4 mod 32 -> conflict-free fragment LDS).
// ===========================================================================
#define GS 36

__device__ __forceinline__ void gemm_tf32(const float* __restrict__ A,
                                          const float* __restrict__ W,
                                          const float* __restrict__ bias,
                                          float* __restrict__ out)
{
    __shared__ unsigned As[128*GS];
    __shared__ unsigned Bs[128*GS];

    const int tid  = threadIdx.x;
    const int warp = tid >> 5, lane = tid & 31;
    const int gid  = lane >> 2, tg = lane & 3;
    const int wR   = warp & 3;      // 0..3  (M)
    const int wC   = warp >> 2;     // 0..1  (N)
    const int row0 = blockIdx.y * 128;
    const int col0 = blockIdx.x * 128;

    float c[16][4];
#pragma unroll
    for (int i = 0; i < 16; i++)
#pragma unroll
        for (int j = 0; j < 4; j++) c[i][j] = 0.f;

    for (int kt = 0; kt < ND; kt += 32) {
#pragma unroll
        for (int u = 0; u < 4; u++) {
            int idx = tid + u*256;
            int r   = idx >> 3;
            int kq  = (idx & 7) << 2;
            float4 a = *(const float4*)(A + (size_t)(row0+r)*ND + kt + kq);
            As[r*GS + kq+0] = f2tf(a.x); As[r*GS + kq+1] = f2tf(a.y);
            As[r*GS + kq+2] = f2tf(a.z); As[r*GS + kq+3] = f2tf(a.w);
            float4 b = *(const float4*)(W + (size_t)(col0+r)*ND + kt + kq);
            Bs[r*GS + kq+0] = f2tf(b.x); Bs[r*GS + kq+1] = f2tf(b.y);
            Bs[r*GS + kq+2] = f2tf(b.z); Bs[r*GS + kq+3] = f2tf(b.w);
        }
        __syncthreads();

#pragma unroll
        for (int ks = 0; ks < 32; ks += 8) {
            unsigned bf[8][2];
#pragma unroll
            for (int j = 0; j < 8; j++) {
                int n = wC*64 + j*8 + gid;
                bf[j][0] = Bs[n*GS + ks + tg];
                bf[j][1] = Bs[n*GS + ks + tg + 4];
            }
#pragma unroll
            for (int mi = 0; mi < 2; mi++) {
                int r = wR*32 + mi*16;
                unsigned a0 = As[(r+gid  )*GS + ks + tg];
                unsigned a1 = As[(r+gid+8)*GS + ks + tg];
                unsigned a2 = As[(r+gid  )*GS + ks + tg + 4];
                unsigned a3 = As[(r+gid+8)*GS + ks + tg + 4];
#pragma unroll
                for (int j = 0; j < 8; j++)
                    mma8(c[mi*8+j], a0, a1, a2, a3, bf[j][0], bf[j][1]);
            }
        }
        __syncthreads();
    }

    // epilogue + bias
#pragma unroll
    for (int mi = 0; mi < 2; mi++) {
#pragma unroll
        for (int j = 0; j < 8; j++) {
            int r   = row0 + wR*32 + mi*16 + gid;
            int col = col0 + wC*64 + j*8 + tg*2;
            float2 o0, o1;
            o0.x = c[mi*8+j][0] + bias[col];
            o0.y = c[mi*8+j][1] + bias[col+1];
            o1.x = c[mi*8+j][2] + bias[col];
            o1.y = c[mi*8+j][3] + bias[col+1];
            *(float2*)(out + (size_t)r*ND + col)     = o0;
            *(float2*)(out + (size_t)(r+8)*ND + col) = o1;
        }
    }
}

__global__ void __launch_bounds__(256,2)
k_qkv(const float* __restrict__ q, const float* __restrict__ k, const float* __restrict__ v,
      const float* __restrict__ Wq, const float* __restrict__ bq,
      const float* __restrict__ Wk, const float* __restrict__ bk,
      const float* __restrict__ Wv, const float* __restrict__ bv)
{
    if      (blockIdx.z == 0) gemm_tf32(q, Wq, bq, g_Q);
    else if (blockIdx.z == 1) gemm_tf32(k, Wk, bk, g_K);
    else                      gemm_tf32(v, Wv, bv, g_V);
}

__global__ void __launch_bounds__(256,2)
k_oproj(const float* __restrict__ Wo, const float* __restrict__ bo)
{
    gemm_tf32(g_ctx, Wo, bo, g_proj);
}

// ===========================================================================
// Flash attention, tensor-core edition.
// CTA = (b, h, 128-q tile), 256 thr = 8 warps; each warp owns 16 q rows.
//  QK^T: warp m16 x n128, k=64       (tf32 mma)
//  PV:   warp m16 x n64,  k=128      (tf32 mma)
// Smem strides: Qs/Ks 68 (=4 mod 32), Vs 72 (=8 mod 32), Ps 132 (=4 mod 32)
//  -> all fragment LDS conflict-free.
// ===========================================================================
#define QS 68
#define KS 68
#define VS 72
#define PS 132
#define SMEM_ATTN ((128*QS + 128*KS + 128*VS + 128*PS)*4)

__global__ void __launch_bounds__(256,1)
k_attn(const float* __restrict__ guide, const float* __restrict__ bias_scale)
{
    extern __shared__ unsigned sm[];
    unsigned* Qs = sm;
    unsigned* Ks = Qs + 128*QS;
    unsigned* Vs = Ks + 128*KS;
    unsigned* Ps = Vs + 128*VS;

    const int tid  = threadIdx.x;
    const int warp = tid >> 5, lane = tid & 31;
    const int gid  = lane >> 2, tg = lane & 3;
    const int q0   = blockIdx.x * 128;
    const int b    = blockIdx.y >> 3;
    const int h    = blockIdx.y & 7;

    const float bs = bias_scale[0];
    const float sp = (bs > 20.f) ? bs : log1pf(__expf(bs));
    const float scale = 0.125f;          // 64^-0.5

    const int r1 = warp*16 + gid;        // this thread's two q rows
    const int r2 = r1 + 8;

    // ---- load Q tile (scale folded, tf32) ----
#pragma unroll
    for (int u = 0; u < 8; u++) {
        int idx = tid + u*256;
        int r   = idx >> 4;
        int dq  = (idx & 15) << 2;
        float4 x = *(const float4*)(g_Q + (size_t)(b*NT + q0 + r)*ND + h*NHD + dq);
        Qs[r*QS + dq+0] = f2tf(x.x*scale);
        Qs[r*QS + dq+1] = f2tf(x.y*scale);
        Qs[r*QS + dq+2] = f2tf(x.z*scale);
        Qs[r*QS + dq+3] = f2tf(x.w*scale);
    }

    float m1 = -1e30f, m2 = -1e30f, l1 = 0.f, l2 = 0.f;
    float o[8][4];
#pragma unroll
    for (int j = 0; j < 8; j++)
#pragma unroll
        for (int i = 0; i < 4; i++) o[j][i] = 0.f;

    for (int t = 0; t < NT; t += 128) {
        __syncthreads();    // prev iter done with Ks/Vs/Ps
        // ---- load K,V tiles (tf32) ----
#pragma unroll
        for (int u = 0; u < 8; u++) {
            int idx = tid + u*256;
            int r   = idx >> 4;
            int dq  = (idx & 15) << 2;
            size_t goff = (size_t)(b*NT + t + r)*ND + h*NHD + dq;
            float4 kx = *(const float4*)(g_K + goff);
            Ks[r*KS + dq+0] = f2tf(kx.x); Ks[r*KS + dq+1] = f2tf(kx.y);
            Ks[r*KS + dq+2] = f2tf(kx.z); Ks[r*KS + dq+3] = f2tf(kx.w);
            float4 vx = *(const float4*)(g_V + goff);
            Vs[r*VS + dq+0] = f2tf(vx.x); Vs[r*VS + dq+1] = f2tf(vx.y);
            Vs[r*VS + dq+2] = f2tf(vx.z); Vs[r*VS + dq+3] = f2tf(vx.w);
        }
        __syncthreads();

        // ---- S = Q K^T (tensor) ----
        float s[16][4];
#pragma unroll
        for (int j = 0; j < 16; j++)
#pragma unroll
            for (int i = 0; i < 4; i++) s[j][i] = 0.f;

#pragma unroll
        for (int ks = 0; ks < 64; ks += 8) {
            int rb = warp*16;
            unsigned a0 = Qs[(rb+gid  )*QS + ks + tg];
            unsigned a1 = Qs[(rb+gid+8)*QS + ks + tg];
            unsigned a2 = Qs[(rb+gid  )*QS + ks + tg + 4];
            unsigned a3 = Qs[(rb+gid+8)*QS + ks + tg + 4];
#pragma unroll
            for (int j = 0; j < 16; j++) {
                int n = j*8 + gid;
                unsigned b0 = Ks[n*KS + ks + tg];
                unsigned b1 = Ks[n*KS + ks + tg + 4];
                mma8(s[j], a0, a1, a2, a3, b0, b1);
            }
        }

        // ---- transport bias + row max ----
        float mx1 = -1e30f, mx2 = -1e30f;
        const size_t base1 = (size_t)(b*NT + q0 + r1)*NT + t;
        const size_t base2 = (size_t)(b*NT + q0 + r2)*NT + t;
#pragma unroll
        for (int j = 0; j < 16; j++) {
            int col = j*8 + 2*tg;
            float2 g1 = *(const float2*)(guide + base1 + col);
            float2 g2 = *(const float2*)(guide + base2 + col);
            s[j][0] += __logf(g1.x + 1e-8f)*sp;
            s[j][1] += __logf(g1.y + 1e-8f)*sp;
            s[j][2] += __logf(g2.x + 1e-8f)*sp;
            s[j][3] += __logf(g2.y + 1e-8f)*sp;
            mx1 = fmaxf(mx1, fmaxf(s[j][0], s[j][1]));
            mx2 = fmaxf(mx2, fmaxf(s[j][2], s[j][3]));
        }
        // row reduce over tg lanes (xor 1,2)
        mx1 = fmaxf(mx1, __shfl_xor_sync(0xffffffffu, mx1, 1));
        mx1 = fmaxf(mx1, __shfl_xor_sync(0xffffffffu, mx1, 2));
        mx2 = fmaxf(mx2, __shfl_xor_sync(0xffffffffu, mx2, 1));
        mx2 = fmaxf(mx2, __shfl_xor_sync(0xffffffffu, mx2, 2));

        float mn1 = fmaxf(m1, mx1), mn2 = fmaxf(m2, mx2);
        float corr1 = __expf(m1 - mn1), corr2 = __expf(m2 - mn2);
        m1 = mn1; m2 = mn2;

        float rs1 = 0.f, rs2 = 0.f;
#pragma unroll
        for (int j = 0; j < 16; j++) {
            int col = j*8 + 2*tg;
            float p0 = __expf(s[j][0] - m1);
            float p1 = __expf(s[j][1] - m1);
            float p2 = __expf(s[j][2] - m2);
            float p3 = __expf(s[j][3] - m2);
            rs1 += p0 + p1;  rs2 += p2 + p3;
            uint2 w1; w1.x = f2tf(p0); w1.y = f2tf(p1);
            uint2 w2; w2.x = f2tf(p2); w2.y = f2tf(p3);
            *(uint2*)(Ps + r1*PS + col) = w1;
            *(uint2*)(Ps + r2*PS + col) = w2;
        }
        rs1 += __shfl_xor_sync(0xffffffffu, rs1, 1);
        rs1 += __shfl_xor_sync(0xffffffffu, rs1, 2);
        rs2 += __shfl_xor_sync(0xffffffffu, rs2, 1);
        rs2 += __shfl_xor_sync(0xffffffffu, rs2, 2);
        l1 = l1*corr1 + rs1;
        l2 = l2*corr2 + rs2;
#pragma unroll
        for (int j = 0; j < 8; j++) {
            o[j][0] *= corr1; o[j][1] *= corr1;
            o[j][2] *= corr2; o[j][3] *= corr2;
        }
        __syncthreads();    // Ps visible

        // ---- acc += P @ V (tensor) ----
#pragma unroll
        for (int ks = 0; ks < 128; ks += 8) {
            int rb = warp*16;
            unsigned a0 = Ps[(rb+gid  )*PS + ks + tg];
            unsigned a1 = Ps[(rb+gid+8)*PS + ks + tg];
            unsigned a2 = Ps[(rb+gid  )*PS + ks + tg + 4];
            unsigned a3 = Ps[(rb+gid+8)*PS + ks + tg + 4];
#pragma unroll
            for (int j = 0; j < 8; j++) {
                int n = j*8 + gid;
                unsigned b0 = Vs[(ks+tg  )*VS + n];
                unsigned b1 = Vs[(ks+tg+4)*VS + n];
                mma8(o[j], a0, a1, a2, a3, b0, b1);
            }
        }
    }

    // ---- normalize + write context ----
    float inv1 = 1.f / l1, inv2 = 1.f / l2;
#pragma unroll
    for (int j = 0; j < 8; j++) {
        int col = h*NHD + j*8 + 2*tg;
        float2 o1, o2;
        o1.x = o[j][0]*inv1; o1.y = o[j][1]*inv1;
        o2.x = o[j][2]*inv2; o2.y = o[j][3]*inv2;
        *(float2*)(g_ctx + (size_t)(b*NT + q0 + r1)*ND + col) = o1;
        *(float2*)(g_ctx + (size_t)(b*NT + q0 + r2)*ND + col) = o2;
    }
}

// ===========================================================================
// Fused residual + gate + LayerNorm.  One 128-thread block per row.
// ===========================================================================
__global__ void __launch_bounds__(128,8)
k_ln(const float* __restrict__ qin, const float* __restrict__ gate,
     const float* __restrict__ gamma, const float* __restrict__ beta,
     float* __restrict__ out)
{
    const int row = blockIdx.x;
    const int t   = threadIdx.x;
    const int wid = t >> 5, lane = t & 31;
    const float sg = 1.f/(1.f + __expf(-gate[0]));

    float y[4];
    float s = 0.f;
#pragma unroll
    for (int u = 0; u < 4; u++) {
        int c = t + u*128;
        y[u] = qin[(size_t)row*ND + c] + sg * g_proj[(size_t)row*ND + c];
        s += y[u];
    }
    __shared__ float red1[4], red2[4];
#pragma unroll
    for (int off = 16; off >= 1; off >>= 1) s += __shfl_xor_sync(0xffffffffu, s, off);
    if (lane == 0) red1[wid] = s;
    __syncthreads();
    float mu = (red1[0]+red1[1]+red1[2]+red1[3]) * (1.f/ND);

    float vs = 0.f;
#pragma unroll
    for (int u = 0; u < 4; u++) { float d = y[u]-mu; vs += d*d; }
#pragma unroll
    for (int off = 16; off >= 1; off >>= 1) vs += __shfl_xor_sync(0xffffffffu, vs, off);
    if (lane == 0) red2[wid] = vs;
    __syncthreads();
    float var  = (red2[0]+red2[1]+red2[2]+red2[3]) * (1.f/ND);
    float rstd = rsqrtf(var + 1e-5f);

#pragma unroll
    for (int u = 0; u < 4; u++) {
        int c = t + u*128;
        out[(size_t)row*ND + c] = (y[u]-mu)*rstd*gamma[c] + beta[c];
    }
}

// ===========================================================================
extern "C" void kernel_launch(void* const* d_in, const int* in_sizes, int n_in,
                              void* d_out, int out_size)
{
    (void)in_sizes; (void)n_in; (void)out_size;
    const float* q          = (const float*)d_in[0];
    const float* k          = (const float*)d_in[1];
    const float* v          = (const float*)d_in[2];
    const float* guide      = (const float*)d_in[3];
    const float* Wq         = (const float*)d_in[4];
    const float* bq         = (const float*)d_in[5];
    const float* Wk         = (const float*)d_in[6];
    const float* bk         = (const float*)d_in[7];
    const float* Wv         = (const float*)d_in[8];
    const float* bv         = (const float*)d_in[9];
    const float* Wo         = (const float*)d_in[10];
    const float* bo         = (const float*)d_in[11];
    const float* ln_gamma   = (const float*)d_in[12];
    const float* ln_beta    = (const float*)d_in[13];
    const float* gate       = (const float*)d_in[14];
    const float* bias_scale = (const float*)d_in[15];
    float* out = (float*)d_out;

    cudaFuncSetAttribute(k_attn, cudaFuncAttributeMaxDynamicSharedMemorySize, SMEM_ATTN);

    // Q/K/V projections (fused across gridDim.z), tf32 tensor cores
    k_qkv<<<dim3(ND/128, NM/128, 3), 256>>>(q, k, v, Wq, bq, Wk, bk, Wv, bv);
    // attention (tf32 tensor cores)
    k_attn<<<dim3(NT/128, NB*NH), 256, SMEM_ATTN>>>(guide, bias_scale);
    // output projection
    k_oproj<<<dim3(ND/128, NM/128), 256>>>(Wo, bo);
    // residual + gate + layernorm
    k_ln<<<NM, 128>>>(q, gate, ln_gamma, ln_beta, out);
}

// round 5
// speedup vs baseline: 3.2565x; 1.3051x over previous
#include <cuda_runtime.h>
#include <cuda_bf16.h>
#include <math.h>

#define NB   4
#define NT   1024
#define ND   512
#define NH   8
#define NHD  64
#define NM   (NB*NT)     // 4096 rows

// ------------------- scratch (device globals; no allocs allowed) ----------
__device__ float g_Q[NM*ND];
__device__ float g_K[NM*ND];
__device__ float g_V[NM*ND];
__device__ float g_ctx[NM*ND];
__device__ float g_proj[NM*ND];
__device__ float g_bias[NB*NT*NT];   // precomputed log(guide+1e-8)*softplus(bs)

// ------------------- bf16 helpers -----------------------------------------
__device__ __forceinline__ unsigned pack_bf16(float lo, float hi) {
    unsigned d;
    asm("cvt.rn.bf16x2.f32 %0, %1, %2;" : "=r"(d) : "f"(hi), "f"(lo));
    return d;
}
__device__ __forceinline__ void mma16(float* c, unsigned a0, unsigned a1,
                                      unsigned a2, unsigned a3,
                                      unsigned b0, unsigned b1) {
    asm volatile(
        "mma.sync.aligned.m16n8k16.row.col.f32.bf16.bf16.f32 "
        "{%0,%1,%2,%3},{%4,%5,%6,%7},{%8,%9},{%0,%1,%2,%3};\n"
        : "+f"(c[0]), "+f"(c[1]), "+f"(c[2]), "+f"(c[3])
        : "r"(a0), "r"(a1), "r"(a2), "r"(a3), "r"(b0), "r"(b1));
}
__device__ __forceinline__ void ldm4(unsigned& r0, unsigned& r1,
                                     unsigned& r2, unsigned& r3, unsigned addr) {
    asm volatile("ldmatrix.sync.aligned.m8n8.x4.shared.b16 {%0,%1,%2,%3}, [%4];"
        : "=r"(r0), "=r"(r1), "=r"(r2), "=r"(r3) : "r"(addr));
}
__device__ __forceinline__ void ldm4t(unsigned& r0, unsigned& r1,
                                      unsigned& r2, unsigned& r3, unsigned addr) {
    asm volatile("ldmatrix.sync.aligned.m8n8.x4.trans.shared.b16 {%0,%1,%2,%3}, [%4];"
        : "=r"(r0), "=r"(r1), "=r"(r2), "=r"(r3) : "r"(addr));
}

// ===========================================================================
// bias precompute: g_bias = log(guide + 1e-8) * softplus(bias_scale)
// ===========================================================================
__global__ void __launch_bounds__(256,8)
k_bias(const float* __restrict__ guide, const float* __restrict__ bias_scale)
{
    const float bs = bias_scale[0];
    const float sp = (bs > 20.f) ? bs : log1pf(__expf(bs));
    size_t i = ((size_t)blockIdx.x*256 + threadIdx.x)*4;
    float4 g = *(const float4*)(guide + i);
    float4 o;
    o.x = __logf(g.x + 1e-8f)*sp;
    o.y = __logf(g.y + 1e-8f)*sp;
    o.z = __logf(g.z + 1e-8f)*sp;
    o.w = __logf(g.w + 1e-8f)*sp;
    *(float4*)(g_bias + i) = o;
}

// ===========================================================================
// bf16 GEMM: out[m,n] = sum_k A[m,k]*W[n,k] + bias[n]  (M=4096,N=512,K=512)
// CTA 128x128, 8 warps (4M x 2N), warp 32x64, ktile=32 (2 k16 mma steps).
// ===========================================================================
#define GW 20

__device__ __forceinline__ void gemm_bf16(const float* __restrict__ A,
                                          const float* __restrict__ W,
                                          const float* __restrict__ bias,
                                          float* __restrict__ out)
{
    __shared__ unsigned As[128*GW];
    __shared__ unsigned Bs[128*GW];

    const int tid  = threadIdx.x;
    const int warp = tid >> 5, lane = tid & 31;
    const int gid  = lane >> 2, tg = lane & 3;
    const int wR   = warp & 3;
    const int wC   = warp >> 2;
    const int row0 = blockIdx.y * 128;
    const int col0 = blockIdx.x * 128;

    float c[16][4];
#pragma unroll
    for (int i = 0; i < 16; i++)
#pragma unroll
        for (int j = 0; j < 4; j++) c[i][j] = 0.f;

    for (int kt = 0; kt < ND; kt += 32) {
#pragma unroll
        for (int u = 0; u < 4; u++) {
            int idx = tid + u*256;
            int r   = idx >> 3;
            int wq  = (idx & 7) << 1;           // word offset 0,2,...,14
            float4 a = *(const float4*)(A + (size_t)(row0+r)*ND + kt + wq*2);
            As[r*GW + wq]   = pack_bf16(a.x, a.y);
            As[r*GW + wq+1] = pack_bf16(a.z, a.w);
            float4 b = *(const float4*)(W + (size_t)(col0+r)*ND + kt + wq*2);
            Bs[r*GW + wq]   = pack_bf16(b.x, b.y);
            Bs[r*GW + wq+1] = pack_bf16(b.z, b.w);
        }
        __syncthreads();

#pragma unroll
        for (int ko = 0; ko < 16; ko += 8) {    // word offset per k16 step
            unsigned bf[8][2];
#pragma unroll
            for (int j = 0; j < 8; j++) {
                int n = wC*64 + j*8 + gid;
                bf[j][0] = Bs[n*GW + ko + tg];
                bf[j][1] = Bs[n*GW + ko + tg + 4];
            }
#pragma unroll
            for (int mi = 0; mi < 2; mi++) {
                int r = wR*32 + mi*16;
                unsigned a0 = As[(r+gid  )*GW + ko + tg];
                unsigned a1 = As[(r+gid+8)*GW + ko + tg];
                unsigned a2 = As[(r+gid  )*GW + ko + tg + 4];
                unsigned a3 = As[(r+gid+8)*GW + ko + tg + 4];
#pragma unroll
                for (int j = 0; j < 8; j++)
                    mma16(c[mi*8+j], a0, a1, a2, a3, bf[j][0], bf[j][1]);
            }
        }
        __syncthreads();
    }

#pragma unroll
    for (int mi = 0; mi < 2; mi++) {
#pragma unroll
        for (int j = 0; j < 8; j++) {
            int r   = row0 + wR*32 + mi*16 + gid;
            int col = col0 + wC*64 + j*8 + tg*2;
            float2 o0, o1;
            o0.x = c[mi*8+j][0] + bias[col];
            o0.y = c[mi*8+j][1] + bias[col+1];
            o1.x = c[mi*8+j][2] + bias[col];
            o1.y = c[mi*8+j][3] + bias[col+1];
            *(float2*)(out + (size_t)r*ND + col)     = o0;
            *(float2*)(out + (size_t)(r+8)*ND + col) = o1;
        }
    }
}

__global__ void __launch_bounds__(256,2)
k_qkv(const float* __restrict__ q, const float* __restrict__ k, const float* __restrict__ v,
      const float* __restrict__ Wq, const float* __restrict__ bq,
      const float* __restrict__ Wk, const float* __restrict__ bk,
      const float* __restrict__ Wv, const float* __restrict__ bv)
{
    if      (blockIdx.z == 0) gemm_bf16(q, Wq, bq, g_Q);
    else if (blockIdx.z == 1) gemm_bf16(k, Wk, bk, g_K);
    else                      gemm_bf16(v, Wv, bv, g_V);
}

__global__ void __launch_bounds__(256,2)
k_oproj(const float* __restrict__ Wo, const float* __restrict__ bo)
{
    gemm_bf16(g_ctx, Wo, bo, g_proj);
}

// ===========================================================================
// Flash attention, bf16 tensor-core + ldmatrix edition.
// CTA = (b,h,128-q tile), 8 warps, each warp 16 q rows.
// NOTE: reads g_bias DIRECTLY (device symbol). Passing it as a host-side
// kernel arg silently bound the HOST shadow copy via GB300 ATS -> zero bias.
// ===========================================================================
#define QW 36
#define PW 68
#define KOFF (128*QW)
#define VOFF (256*QW)
#define POFF (384*QW)
#define SMEM_ATTN ((384*QW + 128*PW)*4)

__global__ void __launch_bounds__(256,2)
k_attn()
{
    extern __shared__ unsigned sm[];
    unsigned* Qs = sm;
    unsigned* Ks = sm + KOFF;
    unsigned* Vs = sm + VOFF;
    unsigned* Ps = sm + POFF;
    const unsigned smb = (unsigned)__cvta_generic_to_shared(sm);
    const float* __restrict__ bias = g_bias;

    const int tid  = threadIdx.x;
    const int warp = tid >> 5, lane = tid & 31;
    const int gid  = lane >> 2, tg = lane & 3;
    const int q0   = blockIdx.x * 128;
    const int b    = blockIdx.y >> 3;
    const int h    = blockIdx.y & 7;
    const float scale = 0.125f;          // 64^-0.5

    const int rb = warp*16;
    const int r1 = rb + gid, r2 = r1 + 8;

    const int li  = lane & 7;
    const int t01 = (lane >> 3) & 1;
    const int t23 = lane >> 4;

    const unsigned aQ = smb + (((rb + t01*8 + li)*QW + t23*4) << 2);
    const unsigned aK = smb + ((KOFF + (t23*8 + li)*QW + t01*4) << 2);
    const unsigned aV = smb + ((VOFF + (t01*8 + li)*QW + t23*4) << 2);
    const unsigned aP = smb + ((POFF + (rb + t01*8 + li)*PW + t23*4) << 2);

    // ---- load Q tile (scale folded, bf16) ----
#pragma unroll
    for (int u = 0; u < 8; u++) {
        int idx = tid + u*256;
        int r   = idx >> 4;
        int wq  = (idx & 15) << 1;
        float4 x = *(const float4*)(g_Q + (size_t)(b*NT + q0 + r)*ND + h*NHD + wq*2);
        Qs[r*QW + wq]   = pack_bf16(x.x*scale, x.y*scale);
        Qs[r*QW + wq+1] = pack_bf16(x.z*scale, x.w*scale);
    }

    float m1 = -1e30f, m2 = -1e30f, l1 = 0.f, l2 = 0.f;
    float o[8][4];
#pragma unroll
    for (int j = 0; j < 8; j++)
#pragma unroll
        for (int i = 0; i < 4; i++) o[j][i] = 0.f;

    for (int t = 0; t < NT; t += 128) {
        __syncthreads();
        // ---- load K,V tiles ----
#pragma unroll
        for (int u = 0; u < 8; u++) {
            int idx = tid + u*256;
            int r   = idx >> 4;
            int wq  = (idx & 15) << 1;
            size_t goff = (size_t)(b*NT + t + r)*ND + h*NHD + wq*2;
            float4 kx = *(const float4*)(g_K + goff);
            Ks[r*QW + wq]   = pack_bf16(kx.x, kx.y);
            Ks[r*QW + wq+1] = pack_bf16(kx.z, kx.w);
            float4 vx = *(const float4*)(g_V + goff);
            Vs[r*QW + wq]   = pack_bf16(vx.x, vx.y);
            Vs[r*QW + wq+1] = pack_bf16(vx.z, vx.w);
        }
        __syncthreads();

        // ---- S = Q K^T ----
        float s[16][4];
#pragma unroll
        for (int j = 0; j < 16; j++)
#pragma unroll
            for (int i = 0; i < 4; i++) s[j][i] = 0.f;

#pragma unroll
        for (int st = 0; st < 4; st++) {
            unsigned a0,a1,a2,a3;
            ldm4(a0,a1,a2,a3, aQ + st*32);
#pragma unroll
            for (int jp = 0; jp < 8; jp++) {
                unsigned b0,b1,b2,b3;
                ldm4(b0,b1,b2,b3, aK + jp*(16*QW*4) + st*32);
                mma16(s[2*jp],   a0,a1,a2,a3, b0,b1);
                mma16(s[2*jp+1], a0,a1,a2,a3, b2,b3);
            }
        }

        // ---- + precomputed transport bias, row max ----
        float mx1 = -1e30f, mx2 = -1e30f;
        const size_t base1 = (size_t)(b*NT + q0 + r1)*NT + t;
        const size_t base2 = (size_t)(b*NT + q0 + r2)*NT + t;
#pragma unroll
        for (int j = 0; j < 16; j++) {
            int col = j*8 + 2*tg;
            float2 g1 = *(const float2*)(bias + base1 + col);
            float2 g2 = *(const float2*)(bias + base2 + col);
            s[j][0] += g1.x;  s[j][1] += g1.y;
            s[j][2] += g2.x;  s[j][3] += g2.y;
            mx1 = fmaxf(mx1, fmaxf(s[j][0], s[j][1]));
            mx2 = fmaxf(mx2, fmaxf(s[j][2], s[j][3]));
        }
        mx1 = fmaxf(mx1, __shfl_xor_sync(0xffffffffu, mx1, 1));
        mx1 = fmaxf(mx1, __shfl_xor_sync(0xffffffffu, mx1, 2));
        mx2 = fmaxf(mx2, __shfl_xor_sync(0xffffffffu, mx2, 1));
        mx2 = fmaxf(mx2, __shfl_xor_sync(0xffffffffu, mx2, 2));

        float mn1 = fmaxf(m1, mx1), mn2 = fmaxf(m2, mx2);
        float corr1 = __expf(m1 - mn1), corr2 = __expf(m2 - mn2);
        m1 = mn1; m2 = mn2;

        float rs1 = 0.f, rs2 = 0.f;
#pragma unroll
        for (int j = 0; j < 16; j++) {
            float p0 = __expf(s[j][0] - m1);
            float p1 = __expf(s[j][1] - m1);
            float p2 = __expf(s[j][2] - m2);
            float p3 = __expf(s[j][3] - m2);
            rs1 += p0 + p1;  rs2 += p2 + p3;
            Ps[r1*PW + j*4 + tg] = pack_bf16(p0, p1);
            Ps[r2*PW + j*4 + tg] = pack_bf16(p2, p3);
        }
        rs1 += __shfl_xor_sync(0xffffffffu, rs1, 1);
        rs1 += __shfl_xor_sync(0xffffffffu, rs1, 2);
        rs2 += __shfl_xor_sync(0xffffffffu, rs2, 1);
        rs2 += __shfl_xor_sync(0xffffffffu, rs2, 2);
        l1 = l1*corr1 + rs1;
        l2 = l2*corr2 + rs2;
#pragma unroll
        for (int j = 0; j < 8; j++) {
            o[j][0] *= corr1; o[j][1] *= corr1;
            o[j][2] *= corr2; o[j][3] *= corr2;
        }
        __syncwarp();                    // Ps rows are warp-private

        // ---- acc += P @ V ----
#pragma unroll
        for (int st = 0; st < 8; st++) {
            unsigned a0,a1,a2,a3;
            ldm4(a0,a1,a2,a3, aP + st*32);
#pragma unroll
            for (int jp = 0; jp < 4; jp++) {
                unsigned b0,b1,b2,b3;
                ldm4t(b0,b1,b2,b3, aV + st*(16*QW*4) + jp*32);
                mma16(o[2*jp],   a0,a1,a2,a3, b0,b1);
                mma16(o[2*jp+1], a0,a1,a2,a3, b2,b3);
            }
        }
    }

    // ---- normalize + write context ----
    float inv1 = 1.f / l1, inv2 = 1.f / l2;
#pragma unroll
    for (int j = 0; j < 8; j++) {
        int col = h*NHD + j*8 + 2*tg;
        float2 o1, o2;
        o1.x = o[j][0]*inv1; o1.y = o[j][1]*inv1;
        o2.x = o[j][2]*inv2; o2.y = o[j][3]*inv2;
        *(float2*)(g_ctx + (size_t)(b*NT + q0 + r1)*ND + col) = o1;
        *(float2*)(g_ctx + (size_t)(b*NT + q0 + r2)*ND + col) = o2;
    }
}

// ===========================================================================
// Fused residual + gate + LayerNorm.  One 128-thread block per row.
// ===========================================================================
__global__ void __launch_bounds__(128,8)
k_ln(const float* __restrict__ qin, const float* __restrict__ gate,
     const float* __restrict__ gamma, const float* __restrict__ beta,
     float* __restrict__ out)
{
    const int row = blockIdx.x;
    const int t   = threadIdx.x;
    const int wid = t >> 5, lane = t & 31;
    const float sg = 1.f/(1.f + __expf(-gate[0]));

    float y[4];
    float s = 0.f;
#pragma unroll
    for (int u = 0; u < 4; u++) {
        int c = t + u*128;
        y[u] = qin[(size_t)row*ND + c] + sg * g_proj[(size_t)row*ND + c];
        s += y[u];
    }
    __shared__ float red1[4], red2[4];
#pragma unroll
    for (int off = 16; off >= 1; off >>= 1) s += __shfl_xor_sync(0xffffffffu, s, off);
    if (lane == 0) red1[wid] = s;
    __syncthreads();
    float mu = (red1[0]+red1[1]+red1[2]+red1[3]) * (1.f/ND);

    float vs = 0.f;
#pragma unroll
    for (int u = 0; u < 4; u++) { float d = y[u]-mu; vs += d*d; }
#pragma unroll
    for (int off = 16; off >= 1; off >>= 1) vs += __shfl_xor_sync(0xffffffffu, vs, off);
    if (lane == 0) red2[wid] = vs;
    __syncthreads();
    float var  = (red2[0]+red2[1]+red2[2]+red2[3]) * (1.f/ND);
    float rstd = rsqrtf(var + 1e-5f);

#pragma unroll
    for (int u = 0; u < 4; u++) {
        int c = t + u*128;
        out[(size_t)row*ND + c] = (y[u]-mu)*rstd*gamma[c] + beta[c];
    }
}

// ===========================================================================
extern "C" void kernel_launch(void* const* d_in, const int* in_sizes, int n_in,
                              void* d_out, int out_size)
{
    (void)in_sizes; (void)n_in; (void)out_size;
    const float* q          = (const float*)d_in[0];
    const float* k          = (const float*)d_in[1];
    const float* v          = (const float*)d_in[2];
    const float* guide      = (const float*)d_in[3];
    const float* Wq         = (const float*)d_in[4];
    const float* bq         = (const float*)d_in[5];
    const float* Wk         = (const float*)d_in[6];
    const float* bk         = (const float*)d_in[7];
    const float* Wv         = (const float*)d_in[8];
    const float* bv         = (const float*)d_in[9];
    const float* Wo         = (const float*)d_in[10];
    const float* bo         = (const float*)d_in[11];
    const float* ln_gamma   = (const float*)d_in[12];
    const float* ln_beta    = (const float*)d_in[13];
    const float* gate       = (const float*)d_in[14];
    const float* bias_scale = (const float*)d_in[15];
    float* out = (float*)d_out;

    cudaFuncSetAttribute(k_attn, cudaFuncAttributeMaxDynamicSharedMemorySize, SMEM_ATTN);

    // bias precompute
    k_bias<<<NB*NT*NT/1024, 256>>>(guide, bias_scale);
    // Q/K/V projections (bf16 tensor cores)
    k_qkv<<<dim3(ND/128, NM/128, 3), 256>>>(q, k, v, Wq, bq, Wk, bk, Wv, bv);
    // attention (bf16 tensor cores, ldmatrix; reads g_bias device symbol)
    k_attn<<<dim3(NT/128, NB*NH), 256, SMEM_ATTN>>>();
    // output projection
    k_oproj<<<dim3(ND/128, NM/128), 256>>>(Wo, bo);
    // residual + gate + layernorm
    k_ln<<<NM, 128>>>(q, gate, ln_gamma, ln_beta, out);
}

// round 6
// speedup vs baseline: 4.0786x; 1.2524x over previous
#include <cuda_runtime.h>
#include <cuda_bf16.h>
#include <math.h>

#define NB   4
#define NT   1024
#define ND   512
#define NH   8
#define NHD  64
#define NM   (NB*NT)     // 4096 rows

// ------------------- scratch (device globals; no allocs allowed) ----------
__device__ float g_Q[NM*ND];
__device__ float g_K[NM*ND];
__device__ float g_V[NM*ND];
__device__ float g_ctx[NM*ND];
__device__ float g_proj[NM*ND];
__device__ float g_bias[NB*NT*NT];   // log(guide+1e-8)*softplus(bs)

// ------------------- bf16 helpers -----------------------------------------
__device__ __forceinline__ unsigned pack_bf16(float lo, float hi) {
    unsigned d;
    asm("cvt.rn.bf16x2.f32 %0, %1, %2;" : "=r"(d) : "f"(hi), "f"(lo));
    return d;
}
__device__ __forceinline__ void mma16(float* c, unsigned a0, unsigned a1,
                                      unsigned a2, unsigned a3,
                                      unsigned b0, unsigned b1) {
    asm volatile(
        "mma.sync.aligned.m16n8k16.row.col.f32.bf16.bf16.f32 "
        "{%0,%1,%2,%3},{%4,%5,%6,%7},{%8,%9},{%0,%1,%2,%3};\n"
        : "+f"(c[0]), "+f"(c[1]), "+f"(c[2]), "+f"(c[3])
        : "r"(a0), "r"(a1), "r"(a2), "r"(a3), "r"(b0), "r"(b1));
}
__device__ __forceinline__ void ldm4(unsigned& r0, unsigned& r1,
                                     unsigned& r2, unsigned& r3, unsigned addr) {
    asm volatile("ldmatrix.sync.aligned.m8n8.x4.shared.b16 {%0,%1,%2,%3}, [%4];"
        : "=r"(r0), "=r"(r1), "=r"(r2), "=r"(r3) : "r"(addr));
}
__device__ __forceinline__ void ldm4t(unsigned& r0, unsigned& r1,
                                      unsigned& r2, unsigned& r3, unsigned addr) {
    asm volatile("ldmatrix.sync.aligned.m8n8.x4.trans.shared.b16 {%0,%1,%2,%3}, [%4];"
        : "=r"(r0), "=r"(r1), "=r"(r2), "=r"(r3) : "r"(addr));
}

// ===========================================================================
// bf16 GEMM: out[m,n] = sum_k A[m,k]*W[n,k] + bias[n]  (M=4096,N=512,K=512)
// CTA tile 128x64, 256 thr = 8 warps (4M x 2N), warp 32x32.
// ktile=32, register-prefetch double-buffered smem, ldmatrix fragments.
// Smem row stride GW=20 words (16 data + 4 pad): conflict-free LDSM.
// ===========================================================================
#define GW 20
#define BUFW ((128+64)*GW)                 // words per buffer (A then B)

__device__ __forceinline__ void gemm_bf16(const float* __restrict__ A,
                                          const float* __restrict__ W,
                                          const float* __restrict__ bias,
                                          float* __restrict__ out,
                                          int bx, int by)
{
    __shared__ unsigned sh[2*BUFW];

    const int tid  = threadIdx.x;
    const int warp = tid >> 5, lane = tid & 31;
    const int gid  = lane >> 2, tg = lane & 3;
    const int wR   = warp & 3;             // 0..3 (M)
    const int wC   = warp >> 2;            // 0..1 (N)
    const int row0 = by * 128;
    const int col0 = bx * 64;

    // per-thread global load offsets (kt term added in-loop)
    size_t aoff[4], boff[2];
    int    sA[4],  sB[2];
#pragma unroll
    for (int u = 0; u < 4; u++) {
        int idx = tid + u*256;             // 0..1023: A 128 rows x 8 float4
        aoff[u] = (size_t)(row0 + (idx>>3))*ND + ((idx&7)<<2);
        sA[u]   = (idx>>3)*GW + ((idx&7)<<1);
    }
#pragma unroll
    for (int u = 0; u < 2; u++) {
        int idx = tid + u*256;             // 0..511: B 64 rows x 8 float4
        boff[u] = (size_t)(col0 + (idx>>3))*ND + ((idx&7)<<2);
        sB[u]   = 128*GW + (idx>>3)*GW + ((idx&7)<<1);
    }

    // prologue: tile 0 -> buffer 0
    float4 pa[4], pb[2];
#pragma unroll
    for (int u = 0; u < 4; u++) pa[u] = *(const float4*)(A + aoff[u]);
#pragma unroll
    for (int u = 0; u < 2; u++) pb[u] = *(const float4*)(W + boff[u]);
#pragma unroll
    for (int u = 0; u < 4; u++) {
        sh[sA[u]]   = pack_bf16(pa[u].x, pa[u].y);
        sh[sA[u]+1] = pack_bf16(pa[u].z, pa[u].w);
    }
#pragma unroll
    for (int u = 0; u < 2; u++) {
        sh[sB[u]]   = pack_bf16(pb[u].x, pb[u].y);
        sh[sB[u]+1] = pack_bf16(pb[u].z, pb[u].w);
    }
    __syncthreads();

    float c[8][4];
#pragma unroll
    for (int i = 0; i < 8; i++)
#pragma unroll
        for (int j = 0; j < 4; j++) c[i][j] = 0.f;

    // per-lane ldmatrix base addresses (bytes)
    const unsigned smb = (unsigned)__cvta_generic_to_shared(sh);
    const int li  = lane & 7;
    const int t01 = (lane >> 3) & 1;
    const int t23 = lane >> 4;
    const unsigned aA = smb + (((wR*32 + t01*8 + li)*GW + t23*4) << 2);
    const unsigned aB = smb + ((128*GW + (wC*32 + t23*8 + li)*GW + t01*4) << 2);
    const unsigned BUFB = BUFW * 4;

    for (int kt = 0; kt < 16; kt++) {
        const unsigned cur = (kt & 1) * BUFB;
        if (kt < 15) {
            const int off = (kt+1) * 32;
#pragma unroll
            for (int u = 0; u < 4; u++) pa[u] = *(const float4*)(A + aoff[u] + off);
#pragma unroll
            for (int u = 0; u < 2; u++) pb[u] = *(const float4*)(W + boff[u] + off);
        }
#pragma unroll
        for (int ko = 0; ko < 2; ko++) {
            const unsigned koff = cur + ko*32;
            unsigned a0[4], a1[4], b0[4], b1[4];
            ldm4(a0[0],a0[1],a0[2],a0[3], aA + koff);
            ldm4(a1[0],a1[1],a1[2],a1[3], aA + koff + 16*GW*4);
            ldm4(b0[0],b0[1],b0[2],b0[3], aB + koff);
            ldm4(b1[0],b1[1],b1[2],b1[3], aB + koff + 16*GW*4);
            mma16(c[0], a0[0],a0[1],a0[2],a0[3], b0[0],b0[1]);
            mma16(c[1], a0[0],a0[1],a0[2],a0[3], b0[2],b0[3]);
            mma16(c[2], a0[0],a0[1],a0[2],a0[3], b1[0],b1[1]);
            mma16(c[3], a0[0],a0[1],a0[2],a0[3], b1[2],b1[3]);
            mma16(c[4], a1[0],a1[1],a1[2],a1[3], b0[0],b0[1]);
            mma16(c[5], a1[0],a1[1],a1[2],a1[3], b0[2],b0[3]);
            mma16(c[6], a1[0],a1[1],a1[2],a1[3], b1[0],b1[1]);
            mma16(c[7], a1[0],a1[1],a1[2],a1[3], b1[2],b1[3]);
        }
        if (kt < 15) {
            const int nxt = ((kt+1) & 1) * BUFW;
#pragma unroll
            for (int u = 0; u < 4; u++) {
                sh[nxt + sA[u]]   = pack_bf16(pa[u].x, pa[u].y);
                sh[nxt + sA[u]+1] = pack_bf16(pa[u].z, pa[u].w);
            }
#pragma unroll
            for (int u = 0; u < 2; u++) {
                sh[nxt + sB[u]]   = pack_bf16(pb[u].x, pb[u].y);
                sh[nxt + sB[u]+1] = pack_bf16(pb[u].z, pb[u].w);
            }
            __syncthreads();
        }
    }

    // epilogue: c[mi*4 + jp*2 + g], rows = wR*32+mi*16+gid (+8), col block (jp*2+g)*8
#pragma unroll
    for (int mi = 0; mi < 2; mi++) {
#pragma unroll
        for (int nb = 0; nb < 4; nb++) {
            int r   = row0 + wR*32 + mi*16 + gid;
            int col = col0 + wC*32 + nb*8 + tg*2;
            float* cc = c[mi*4 + nb];
            float2 o0, o1;
            o0.x = cc[0] + bias[col];
            o0.y = cc[1] + bias[col+1];
            o1.x = cc[2] + bias[col];
            o1.y = cc[3] + bias[col+1];
            *(float2*)(out + (size_t)r*ND + col)     = o0;
            *(float2*)(out + (size_t)(r+8)*ND + col) = o1;
        }
    }
}

// ===========================================================================
// Fused QKV projections + bias precompute.
// grid (8, 32, 4): z==0 -> bias blocks (scheduled first, HBM-bound,
// overlaps the tensor-bound gemm blocks); z==1/2/3 -> Q/K/V gemm.
// ===========================================================================
__global__ void __launch_bounds__(256,2)
k_qkvb(const float* __restrict__ q, const float* __restrict__ k, const float* __restrict__ v,
       const float* __restrict__ Wq, const float* __restrict__ bq,
       const float* __restrict__ Wk, const float* __restrict__ bk,
       const float* __restrict__ Wv, const float* __restrict__ bv,
       const float* __restrict__ guide, const float* __restrict__ bias_scale)
{
    if (blockIdx.z == 0) {
        // bias: 256 blocks x 256 thr x 16 float4 = 16.7M floats
        const float bs = bias_scale[0];
        const float sp = (bs > 20.f) ? bs : log1pf(__expf(bs));
        const size_t base = (size_t)(blockIdx.y*8 + blockIdx.x)*256 + threadIdx.x;
#pragma unroll 2
        for (int it = 0; it < 16; it++) {
            size_t i = (base + (size_t)it*65536) * 4;
            float4 g = *(const float4*)(guide + i);
            float4 o;
            o.x = __logf(g.x + 1e-8f)*sp;
            o.y = __logf(g.y + 1e-8f)*sp;
            o.z = __logf(g.z + 1e-8f)*sp;
            o.w = __logf(g.w + 1e-8f)*sp;
            *(float4*)(g_bias + i) = o;
        }
    }
    else if (blockIdx.z == 1) gemm_bf16(q, Wq, bq, g_Q, blockIdx.x, blockIdx.y);
    else if (blockIdx.z == 2) gemm_bf16(k, Wk, bk, g_K, blockIdx.x, blockIdx.y);
    else                      gemm_bf16(v, Wv, bv, g_V, blockIdx.x, blockIdx.y);
}

__global__ void __launch_bounds__(256,2)
k_oproj(const float* __restrict__ Wo, const float* __restrict__ bo)
{
    gemm_bf16(g_ctx, Wo, bo, g_proj, blockIdx.x, blockIdx.y);
}

// ===========================================================================
// Flash attention, bf16 tensor-core + ldmatrix.
// grid (h=8 fastest, qtile=8, b=4): head-CTAs sharing a bias tile are
// co-resident -> g_bias HBM-fetched once, L2-served for the other 7 heads.
// Reads g_bias as device symbol (host-arg of __device__ global binds the
// host shadow via GB300 ATS -- silent zero-bias bug, R4).
// ===========================================================================
#define QW 36
#define PW 68
#define KOFF (128*QW)
#define VOFF (256*QW)
#define POFF (384*QW)
#define SMEM_ATTN ((384*QW + 128*PW)*4)

__global__ void __launch_bounds__(256,2)
k_attn()
{
    extern __shared__ unsigned sm[];
    unsigned* Qs = sm;
    unsigned* Ks = sm + KOFF;
    unsigned* Vs = sm + VOFF;
    unsigned* Ps = sm + POFF;
    const unsigned smb = (unsigned)__cvta_generic_to_shared(sm);
    const float* __restrict__ bias = g_bias;

    const int tid  = threadIdx.x;
    const int warp = tid >> 5, lane = tid & 31;
    const int gid  = lane >> 2, tg = lane & 3;
    const int h    = blockIdx.x;
    const int q0   = blockIdx.y * 128;
    const int b    = blockIdx.z;
    const float scale = 0.125f;          // 64^-0.5

    const int rb = warp*16;
    const int r1 = rb + gid, r2 = r1 + 8;

    const int li  = lane & 7;
    const int t01 = (lane >> 3) & 1;
    const int t23 = lane >> 4;

    const unsigned aQ = smb + (((rb + t01*8 + li)*QW + t23*4) << 2);
    const unsigned aK = smb + ((KOFF + (t23*8 + li)*QW + t01*4) << 2);
    const unsigned aV = smb + ((VOFF + (t01*8 + li)*QW + t23*4) << 2);
    const unsigned aP = smb + ((POFF + (rb + t01*8 + li)*PW + t23*4) << 2);

    // ---- load Q tile (scale folded, bf16) ----
#pragma unroll
    for (int u = 0; u < 8; u++) {
        int idx = tid + u*256;
        int r   = idx >> 4;
        int wq  = (idx & 15) << 1;
        float4 x = *(const float4*)(g_Q + (size_t)(b*NT + q0 + r)*ND + h*NHD + wq*2);
        Qs[r*QW + wq]   = pack_bf16(x.x*scale, x.y*scale);
        Qs[r*QW + wq+1] = pack_bf16(x.z*scale, x.w*scale);
    }

    float m1 = -1e30f, m2 = -1e30f, l1 = 0.f, l2 = 0.f;
    float o[8][4];
#pragma unroll
    for (int j = 0; j < 8; j++)
#pragma unroll
        for (int i = 0; i < 4; i++) o[j][i] = 0.f;

    for (int t = 0; t < NT; t += 128) {
        __syncthreads();
        // ---- load K,V tiles ----
#pragma unroll
        for (int u = 0; u < 8; u++) {
            int idx = tid + u*256;
            int r   = idx >> 4;
            int wq  = (idx & 15) << 1;
            size_t goff = (size_t)(b*NT + t + r)*ND + h*NHD + wq*2;
            float4 kx = *(const float4*)(g_K + goff);
            Ks[r*QW + wq]   = pack_bf16(kx.x, kx.y);
            Ks[r*QW + wq+1] = pack_bf16(kx.z, kx.w);
            float4 vx = *(const float4*)(g_V + goff);
            Vs[r*QW + wq]   = pack_bf16(vx.x, vx.y);
            Vs[r*QW + wq+1] = pack_bf16(vx.z, vx.w);
        }
        __syncthreads();

        // ---- S = Q K^T ----
        float s[16][4];
#pragma unroll
        for (int j = 0; j < 16; j++)
#pragma unroll
            for (int i = 0; i < 4; i++) s[j][i] = 0.f;

#pragma unroll
        for (int st = 0; st < 4; st++) {
            unsigned a0,a1,a2,a3;
            ldm4(a0,a1,a2,a3, aQ + st*32);
#pragma unroll
            for (int jp = 0; jp < 8; jp++) {
                unsigned b0,b1,b2,b3;
                ldm4(b0,b1,b2,b3, aK + jp*(16*QW*4) + st*32);
                mma16(s[2*jp],   a0,a1,a2,a3, b0,b1);
                mma16(s[2*jp+1], a0,a1,a2,a3, b2,b3);
            }
        }

        // ---- + precomputed transport bias, row max ----
        float mx1 = -1e30f, mx2 = -1e30f;
        const size_t base1 = (size_t)(b*NT + q0 + r1)*NT + t;
        const size_t base2 = (size_t)(b*NT + q0 + r2)*NT + t;
#pragma unroll
        for (int j = 0; j < 16; j++) {
            int col = j*8 + 2*tg;
            float2 g1 = *(const float2*)(bias + base1 + col);
            float2 g2 = *(const float2*)(bias + base2 + col);
            s[j][0] += g1.x;  s[j][1] += g1.y;
            s[j][2] += g2.x;  s[j][3] += g2.y;
            mx1 = fmaxf(mx1, fmaxf(s[j][0], s[j][1]));
            mx2 = fmaxf(mx2, fmaxf(s[j][2], s[j][3]));
        }
        mx1 = fmaxf(mx1, __shfl_xor_sync(0xffffffffu, mx1, 1));
        mx1 = fmaxf(mx1, __shfl_xor_sync(0xffffffffu, mx1, 2));
        mx2 = fmaxf(mx2, __shfl_xor_sync(0xffffffffu, mx2, 1));
        mx2 = fmaxf(mx2, __shfl_xor_sync(0xffffffffu, mx2, 2));

        float mn1 = fmaxf(m1, mx1), mn2 = fmaxf(m2, mx2);
        float corr1 = __expf(m1 - mn1), corr2 = __expf(m2 - mn2);
        m1 = mn1; m2 = mn2;

        float rs1 = 0.f, rs2 = 0.f;
#pragma unroll
        for (int j = 0; j < 16; j++) {
            float p0 = __expf(s[j][0] - m1);
            float p1 = __expf(s[j][1] - m1);
            float p2 = __expf(s[j][2] - m2);
            float p3 = __expf(s[j][3] - m2);
            rs1 += p0 + p1;  rs2 += p2 + p3;
            Ps[r1*PW + j*4 + tg] = pack_bf16(p0, p1);
            Ps[r2*PW + j*4 + tg] = pack_bf16(p2, p3);
        }
        rs1 += __shfl_xor_sync(0xffffffffu, rs1, 1);
        rs1 += __shfl_xor_sync(0xffffffffu, rs1, 2);
        rs2 += __shfl_xor_sync(0xffffffffu, rs2, 1);
        rs2 += __shfl_xor_sync(0xffffffffu, rs2, 2);
        l1 = l1*corr1 + rs1;
        l2 = l2*corr2 + rs2;
#pragma unroll
        for (int j = 0; j < 8; j++) {
            o[j][0] *= corr1; o[j][1] *= corr1;
            o[j][2] *= corr2; o[j][3] *= corr2;
        }
        __syncwarp();                    // Ps rows are warp-private

        // ---- acc += P @ V ----
#pragma unroll
        for (int st = 0; st < 8; st++) {
            unsigned a0,a1,a2,a3;
            ldm4(a0,a1,a2,a3, aP + st*32);
#pragma unroll
            for (int jp = 0; jp < 4; jp++) {
                unsigned b0,b1,b2,b3;
                ldm4t(b0,b1,b2,b3, aV + st*(16*QW*4) + jp*32);
                mma16(o[2*jp],   a0,a1,a2,a3, b0,b1);
                mma16(o[2*jp+1], a0,a1,a2,a3, b2,b3);
            }
        }
    }

    // ---- normalize + write context ----
    float inv1 = 1.f / l1, inv2 = 1.f / l2;
#pragma unroll
    for (int j = 0; j < 8; j++) {
        int col = h*NHD + j*8 + 2*tg;
        float2 o1, o2;
        o1.x = o[j][0]*inv1; o1.y = o[j][1]*inv1;
        o2.x = o[j][2]*inv2; o2.y = o[j][3]*inv2;
        *(float2*)(g_ctx + (size_t)(b*NT + q0 + r1)*ND + col) = o1;
        *(float2*)(g_ctx + (size_t)(b*NT + q0 + r2)*ND + col) = o2;
    }
}

// ===========================================================================
// Fused residual + gate + LayerNorm.  One 128-thread block per row.
// ===========================================================================
__global__ void __launch_bounds__(128,8)
k_ln(const float* __restrict__ qin, const float* __restrict__ gate,
     const float* __restrict__ gamma, const float* __restrict__ beta,
     float* __restrict__ out)
{
    const int row = blockIdx.x;
    const int t   = threadIdx.x;
    const int wid = t >> 5, lane = t & 31;
    const float sg = 1.f/(1.f + __expf(-gate[0]));

    float y[4];
    float s = 0.f;
#pragma unroll
    for (int u = 0; u < 4; u++) {
        int c = t + u*128;
        y[u] = qin[(size_t)row*ND + c] + sg * g_proj[(size_t)row*ND + c];
        s += y[u];
    }
    __shared__ float red1[4], red2[4];
#pragma unroll
    for (int off = 16; off >= 1; off >>= 1) s += __shfl_xor_sync(0xffffffffu, s, off);
    if (lane == 0) red1[wid] = s;
    __syncthreads();
    float mu = (red1[0]+red1[1]+red1[2]+red1[3]) * (1.f/ND);

    float vs = 0.f;
#pragma unroll
    for (int u = 0; u < 4; u++) { float d = y[u]-mu; vs += d*d; }
#pragma unroll
    for (int off = 16; off >= 1; off >>= 1) vs += __shfl_xor_sync(0xffffffffu, vs, off);
    if (lane == 0) red2[wid] = vs;
    __syncthreads();
    float var  = (red2[0]+red2[1]+red2[2]+red2[3]) * (1.f/ND);
    float rstd = rsqrtf(var + 1e-5f);

#pragma unroll
    for (int u = 0; u < 4; u++) {
        int c = t + u*128;
        out[(size_t)row*ND + c] = (y[u]-mu)*rstd*gamma[c] + beta[c];
    }
}

// ===========================================================================
extern "C" void kernel_launch(void* const* d_in, const int* in_sizes, int n_in,
                              void* d_out, int out_size)
{
    (void)in_sizes; (void)n_in; (void)out_size;
    const float* q          = (const float*)d_in[0];
    const float* k          = (const float*)d_in[1];
    const float* v          = (const float*)d_in[2];
    const float* guide      = (const float*)d_in[3];
    const float* Wq         = (const float*)d_in[4];
    const float* bq         = (const float*)d_in[5];
    const float* Wk         = (const float*)d_in[6];
    const float* bk         = (const float*)d_in[7];
    const float* Wv         = (const float*)d_in[8];
    const float* bv         = (const float*)d_in[9];
    const float* Wo         = (const float*)d_in[10];
    const float* bo         = (const float*)d_in[11];
    const float* ln_gamma   = (const float*)d_in[12];
    const float* ln_beta    = (const float*)d_in[13];
    const float* gate       = (const float*)d_in[14];
    const float* bias_scale = (const float*)d_in[15];
    float* out = (float*)d_out;

    cudaFuncSetAttribute(k_attn, cudaFuncAttributeMaxDynamicSharedMemorySize, SMEM_ATTN);

    // fused bias precompute (z=0) + Q/K/V projections (z=1..3)
    k_qkvb<<<dim3(8, 32, 4), 256>>>(q, k, v, Wq, bq, Wk, bk, Wv, bv,
                                    guide, bias_scale);
    // attention (h varies fastest for bias L2 reuse)
    k_attn<<<dim3(NH, NT/128, NB), 256, SMEM_ATTN>>>();
    // output projection
    k_oproj<<<dim3(8, 32), 256>>>(Wo, bo);
    // residual + gate + layernorm
    k_ln<<<NM, 128>>>(q, gate, ln_gamma, ln_beta, out);
}

// round 7
// speedup vs baseline: 4.2343x; 1.0382x over previous
#include <cuda_runtime.h>
#include <cuda_bf16.h>
#include <math.h>

#define NB   4
#define NT   1024
#define ND   512
#define NH   8
#define NHD  64
#define NM   (NB*NT)     // 4096 rows
#define NDW  (ND/2)      // 256 bf16x2 words per row

// ------------------- scratch (device globals; no allocs allowed) ----------
__device__ unsigned g_Qb[NM*NDW];    // bf16x2, Q prescaled by 0.125
__device__ unsigned g_Kb[NM*NDW];
__device__ unsigned g_Vb[NM*NDW];
__device__ unsigned g_ctxb[NM*NDW];  // bf16x2 context
__device__ float    g_proj[NM*ND];
__device__ float    g_bias[NB*NT*NT];

// ------------------- helpers ----------------------------------------------
__device__ __forceinline__ unsigned pack_bf16(float lo, float hi) {
    unsigned d;
    asm("cvt.rn.bf16x2.f32 %0, %1, %2;" : "=r"(d) : "f"(hi), "f"(lo));
    return d;
}
__device__ __forceinline__ void mma16(float* c, unsigned a0, unsigned a1,
                                      unsigned a2, unsigned a3,
                                      unsigned b0, unsigned b1) {
    asm volatile(
        "mma.sync.aligned.m16n8k16.row.col.f32.bf16.bf16.f32 "
        "{%0,%1,%2,%3},{%4,%5,%6,%7},{%8,%9},{%0,%1,%2,%3};\n"
        : "+f"(c[0]), "+f"(c[1]), "+f"(c[2]), "+f"(c[3])
        : "r"(a0), "r"(a1), "r"(a2), "r"(a3), "r"(b0), "r"(b1));
}
__device__ __forceinline__ void ldm4(unsigned& r0, unsigned& r1,
                                     unsigned& r2, unsigned& r3, unsigned addr) {
    asm volatile("ldmatrix.sync.aligned.m8n8.x4.shared.b16 {%0,%1,%2,%3}, [%4];"
        : "=r"(r0), "=r"(r1), "=r"(r2), "=r"(r3) : "r"(addr));
}
__device__ __forceinline__ void ldm4t(unsigned& r0, unsigned& r1,
                                      unsigned& r2, unsigned& r3, unsigned addr) {
    asm volatile("ldmatrix.sync.aligned.m8n8.x4.trans.shared.b16 {%0,%1,%2,%3}, [%4];"
        : "=r"(r0), "=r"(r1), "=r"(r2), "=r"(r3) : "r"(addr));
}
__device__ __forceinline__ void cpa16(unsigned saddr, const unsigned* g) {
    asm volatile("cp.async.ca.shared.global [%0], [%1], 16;\n" :: "r"(saddr), "l"(g));
}
__device__ __forceinline__ void cpa_commit() {
    asm volatile("cp.async.commit_group;\n");
}
template<int N> __device__ __forceinline__ void cpa_wait() {
    asm volatile("cp.async.wait_group %0;\n" :: "n"(N));
}

// ===========================================================================
// GEMM core: 128x64 CTA, 8 warps (4M x 2N), warp 32x32, ktile=32,
// register-prefetch double-buffered smem, ldmatrix fragments.
// Variant 1: A fp32 in, bf16x2 out (QKV; oscale folds Q's 0.125)
// Variant 2: A bf16x2 in, fp32 out (O-proj)
// ===========================================================================
#define GW 20
#define BUFW ((128+64)*GW)

__device__ __forceinline__ void gemm_f2b(const float* __restrict__ A,
                                         const float* __restrict__ W,
                                         const float* __restrict__ bias,
                                         unsigned* __restrict__ out,
                                         float oscale, int bx, int by)
{
    __shared__ unsigned sh[2*BUFW];
    const int tid  = threadIdx.x;
    const int warp = tid >> 5, lane = tid & 31;
    const int gid  = lane >> 2, tg = lane & 3;
    const int wR   = warp & 3, wC = warp >> 2;
    const int row0 = by * 128, col0 = bx * 64;

    size_t aoff[4], boff[2];
    int    sA[4],  sB[2];
#pragma unroll
    for (int u = 0; u < 4; u++) {
        int idx = tid + u*256;
        aoff[u] = (size_t)(row0 + (idx>>3))*ND + ((idx&7)<<2);
        sA[u]   = (idx>>3)*GW + ((idx&7)<<1);
    }
#pragma unroll
    for (int u = 0; u < 2; u++) {
        int idx = tid + u*256;
        boff[u] = (size_t)(col0 + (idx>>3))*ND + ((idx&7)<<2);
        sB[u]   = 128*GW + (idx>>3)*GW + ((idx&7)<<1);
    }

    float4 pa[4], pb[2];
#pragma unroll
    for (int u = 0; u < 4; u++) pa[u] = *(const float4*)(A + aoff[u]);
#pragma unroll
    for (int u = 0; u < 2; u++) pb[u] = *(const float4*)(W + boff[u]);
#pragma unroll
    for (int u = 0; u < 4; u++) {
        sh[sA[u]]   = pack_bf16(pa[u].x, pa[u].y);
        sh[sA[u]+1] = pack_bf16(pa[u].z, pa[u].w);
    }
#pragma unroll
    for (int u = 0; u < 2; u++) {
        sh[sB[u]]   = pack_bf16(pb[u].x, pb[u].y);
        sh[sB[u]+1] = pack_bf16(pb[u].z, pb[u].w);
    }
    __syncthreads();

    float c[8][4];
#pragma unroll
    for (int i = 0; i < 8; i++)
#pragma unroll
        for (int j = 0; j < 4; j++) c[i][j] = 0.f;

    const unsigned smb = (unsigned)__cvta_generic_to_shared(sh);
    const int li  = lane & 7;
    const int t01 = (lane >> 3) & 1;
    const int t23 = lane >> 4;
    const unsigned aA = smb + (((wR*32 + t01*8 + li)*GW + t23*4) << 2);
    const unsigned aB = smb + ((128*GW + (wC*32 + t23*8 + li)*GW + t01*4) << 2);
    const unsigned BUFB = BUFW * 4;

    for (int kt = 0; kt < 16; kt++) {
        const unsigned cur = (kt & 1) * BUFB;
        if (kt < 15) {
            const int off = (kt+1) * 32;
#pragma unroll
            for (int u = 0; u < 4; u++) pa[u] = *(const float4*)(A + aoff[u] + off);
#pragma unroll
            for (int u = 0; u < 2; u++) pb[u] = *(const float4*)(W + boff[u] + off);
        }
#pragma unroll
        for (int ko = 0; ko < 2; ko++) {
            const unsigned koff = cur + ko*32;
            unsigned a0[4], a1[4], b0[4], b1[4];
            ldm4(a0[0],a0[1],a0[2],a0[3], aA + koff);
            ldm4(a1[0],a1[1],a1[2],a1[3], aA + koff + 16*GW*4);
            ldm4(b0[0],b0[1],b0[2],b0[3], aB + koff);
            ldm4(b1[0],b1[1],b1[2],b1[3], aB + koff + 16*GW*4);
            mma16(c[0], a0[0],a0[1],a0[2],a0[3], b0[0],b0[1]);
            mma16(c[1], a0[0],a0[1],a0[2],a0[3], b0[2],b0[3]);
            mma16(c[2], a0[0],a0[1],a0[2],a0[3], b1[0],b1[1]);
            mma16(c[3], a0[0],a0[1],a0[2],a0[3], b1[2],b1[3]);
            mma16(c[4], a1[0],a1[1],a1[2],a1[3], b0[0],b0[1]);
            mma16(c[5], a1[0],a1[1],a1[2],a1[3], b0[2],b0[3]);
            mma16(c[6], a1[0],a1[1],a1[2],a1[3], b1[0],b1[1]);
            mma16(c[7], a1[0],a1[1],a1[2],a1[3], b1[2],b1[3]);
        }
        if (kt < 15) {
            const int nxt = ((kt+1) & 1) * BUFW;
#pragma unroll
            for (int u = 0; u < 4; u++) {
                sh[nxt + sA[u]]   = pack_bf16(pa[u].x, pa[u].y);
                sh[nxt + sA[u]+1] = pack_bf16(pa[u].z, pa[u].w);
            }
#pragma unroll
            for (int u = 0; u < 2; u++) {
                sh[nxt + sB[u]]   = pack_bf16(pb[u].x, pb[u].y);
                sh[nxt + sB[u]+1] = pack_bf16(pb[u].z, pb[u].w);
            }
            __syncthreads();
        }
    }

    // epilogue: bf16x2 packed output, scale folded
#pragma unroll
    for (int mi = 0; mi < 2; mi++) {
#pragma unroll
        for (int nb = 0; nb < 4; nb++) {
            int r   = row0 + wR*32 + mi*16 + gid;
            int col = col0 + wC*32 + nb*8 + tg*2;
            float* cc = c[mi*4 + nb];
            out[((size_t)r*ND + col) >> 1] =
                pack_bf16((cc[0]+bias[col])*oscale, (cc[1]+bias[col+1])*oscale);
            out[((size_t)(r+8)*ND + col) >> 1] =
                pack_bf16((cc[2]+bias[col])*oscale, (cc[3]+bias[col+1])*oscale);
        }
    }
}

__device__ __forceinline__ void gemm_b2f(const unsigned* __restrict__ A,   // bf16x2
                                         const float* __restrict__ W,
                                         const float* __restrict__ bias,
                                         float* __restrict__ out,
                                         int bx, int by)
{
    __shared__ unsigned sh[2*BUFW];
    const int tid  = threadIdx.x;
    const int warp = tid >> 5, lane = tid & 31;
    const int gid  = lane >> 2, tg = lane & 3;
    const int wR   = warp & 3, wC = warp >> 2;
    const int row0 = by * 128, col0 = bx * 64;

    size_t aoff[2], boff[2];
    int    sA[2],  sB[2];
#pragma unroll
    for (int u = 0; u < 2; u++) {
        int idx = tid + u*256;             // 512 chunks: A 128 rows x 4 uint4
        aoff[u] = (size_t)(row0 + (idx>>2))*NDW + ((idx&3)<<2);
        sA[u]   = (idx>>2)*GW + ((idx&3)<<2);
        boff[u] = (size_t)(col0 + (idx>>3))*ND + ((idx&7)<<2);
        sB[u]   = 128*GW + (idx>>3)*GW + ((idx&7)<<1);
    }

    uint4  pa[2];
    float4 pb[2];
#pragma unroll
    for (int u = 0; u < 2; u++) {
        pa[u] = *(const uint4*)(A + aoff[u]);
        pb[u] = *(const float4*)(W + boff[u]);
    }
#pragma unroll
    for (int u = 0; u < 2; u++) {
        *(uint4*)(sh + sA[u]) = pa[u];
        sh[sB[u]]   = pack_bf16(pb[u].x, pb[u].y);
        sh[sB[u]+1] = pack_bf16(pb[u].z, pb[u].w);
    }
    __syncthreads();

    float c[8][4];
#pragma unroll
    for (int i = 0; i < 8; i++)
#pragma unroll
        for (int j = 0; j < 4; j++) c[i][j] = 0.f;

    const unsigned smb = (unsigned)__cvta_generic_to_shared(sh);
    const int li  = lane & 7;
    const int t01 = (lane >> 3) & 1;
    const int t23 = lane >> 4;
    const unsigned aA = smb + (((wR*32 + t01*8 + li)*GW + t23*4) << 2);
    const unsigned aB = smb + ((128*GW + (wC*32 + t23*8 + li)*GW + t01*4) << 2);
    const unsigned BUFB = BUFW * 4;

    for (int kt = 0; kt < 16; kt++) {
        const unsigned cur = (kt & 1) * BUFB;
        if (kt < 15) {
            const int offw = (kt+1) * 16;
            const int offf = (kt+1) * 32;
#pragma unroll
            for (int u = 0; u < 2; u++) {
                pa[u] = *(const uint4*)(A + aoff[u] + offw);
                pb[u] = *(const float4*)(W + boff[u] + offf);
            }
        }
#pragma unroll
        for (int ko = 0; ko < 2; ko++) {
            const unsigned koff = cur + ko*32;
            unsigned a0[4], a1[4], b0[4], b1[4];
            ldm4(a0[0],a0[1],a0[2],a0[3], aA + koff);
            ldm4(a1[0],a1[1],a1[2],a1[3], aA + koff + 16*GW*4);
            ldm4(b0[0],b0[1],b0[2],b0[3], aB + koff);
            ldm4(b1[0],b1[1],b1[2],b1[3], aB + koff + 16*GW*4);
            mma16(c[0], a0[0],a0[1],a0[2],a0[3], b0[0],b0[1]);
            mma16(c[1], a0[0],a0[1],a0[2],a0[3], b0[2],b0[3]);
            mma16(c[2], a0[0],a0[1],a0[2],a0[3], b1[0],b1[1]);
            mma16(c[3], a0[0],a0[1],a0[2],a0[3], b1[2],b1[3]);
            mma16(c[4], a1[0],a1[1],a1[2],a1[3], b0[0],b0[1]);
            mma16(c[5], a1[0],a1[1],a1[2],a1[3], b0[2],b0[3]);
            mma16(c[6], a1[0],a1[1],a1[2],a1[3], b1[0],b1[1]);
            mma16(c[7], a1[0],a1[1],a1[2],a1[3], b1[2],b1[3]);
        }
        if (kt < 15) {
            const int nxt = ((kt+1) & 1) * BUFW;
#pragma unroll
            for (int u = 0; u < 2; u++) {
                *(uint4*)(sh + nxt + sA[u]) = pa[u];
                sh[nxt + sB[u]]   = pack_bf16(pb[u].x, pb[u].y);
                sh[nxt + sB[u]+1] = pack_bf16(pb[u].z, pb[u].w);
            }
            __syncthreads();
        }
    }

#pragma unroll
    for (int mi = 0; mi < 2; mi++) {
#pragma unroll
        for (int nb = 0; nb < 4; nb++) {
            int r   = row0 + wR*32 + mi*16 + gid;
            int col = col0 + wC*32 + nb*8 + tg*2;
            float* cc = c[mi*4 + nb];
            float2 o0, o1;
            o0.x = cc[0] + bias[col];
            o0.y = cc[1] + bias[col+1];
            o1.x = cc[2] + bias[col];
            o1.y = cc[3] + bias[col+1];
            *(float2*)(out + (size_t)r*ND + col)     = o0;
            *(float2*)(out + (size_t)(r+8)*ND + col) = o1;
        }
    }
}

// ===========================================================================
// Fused QKV projections (bf16 out, Q prescaled) + bias precompute (z==0).
// ===========================================================================
__global__ void __launch_bounds__(256,2)
k_qkvb(const float* __restrict__ q, const float* __restrict__ k, const float* __restrict__ v,
       const float* __restrict__ Wq, const float* __restrict__ bq,
       const float* __restrict__ Wk, const float* __restrict__ bk,
       const float* __restrict__ Wv, const float* __restrict__ bv,
       const float* __restrict__ guide, const float* __restrict__ bias_scale)
{
    if (blockIdx.z == 0) {
        const float bs = bias_scale[0];
        const float sp = (bs > 20.f) ? bs : log1pf(__expf(bs));
        const size_t base = (size_t)(blockIdx.y*8 + blockIdx.x)*256 + threadIdx.x;
#pragma unroll 2
        for (int it = 0; it < 16; it++) {
            size_t i = (base + (size_t)it*65536) * 4;
            float4 g = *(const float4*)(guide + i);
            float4 o;
            o.x = __logf(g.x + 1e-8f)*sp;
            o.y = __logf(g.y + 1e-8f)*sp;
            o.z = __logf(g.z + 1e-8f)*sp;
            o.w = __logf(g.w + 1e-8f)*sp;
            *(float4*)(g_bias + i) = o;
        }
    }
    else if (blockIdx.z == 1) gemm_f2b(q, Wq, bq, g_Qb, 0.125f, blockIdx.x, blockIdx.y);
    else if (blockIdx.z == 2) gemm_f2b(k, Wk, bk, g_Kb, 1.0f,   blockIdx.x, blockIdx.y);
    else                      gemm_f2b(v, Wv, bv, g_Vb, 1.0f,   blockIdx.x, blockIdx.y);
}

__global__ void __launch_bounds__(256,2)
k_oproj(const float* __restrict__ Wo, const float* __restrict__ bo)
{
    gemm_b2f(g_ctxb, Wo, bo, g_proj, blockIdx.x, blockIdx.y);
}

// ===========================================================================
// Flash attention: bf16 mma + ldmatrix, cp.async double-buffered K/V,
// P kept entirely in registers (softmax output IS the PV A-fragment).
// Smem (words): Q [0,4608) | K0 | V0 | K1 | V1  -> 90 KB, occ 2.
// ===========================================================================
#define QW 36
#define SQ  0
#define SK0 (128*QW)
#define SV0 (256*QW)
#define SK1 (384*QW)
#define SV1 (512*QW)
#define SMEM_ATTN (640*QW*4)

__global__ void __launch_bounds__(256,2)
k_attn()
{
    extern __shared__ unsigned sm[];
    const unsigned smb = (unsigned)__cvta_generic_to_shared(sm);
    const float* __restrict__ bias = g_bias;     // device symbol (R4 ATS bug)

    const int tid  = threadIdx.x;
    const int warp = tid >> 5, lane = tid & 31;
    const int gid  = lane >> 2, tg = lane & 3;
    const int h    = blockIdx.x;
    const int q0   = blockIdx.y * 128;
    const int b    = blockIdx.z;

    const int rb = warp*16;
    const int r1 = rb + gid, r2 = r1 + 8;

    const int li  = lane & 7;
    const int t01 = (lane >> 3) & 1;
    const int t23 = lane >> 4;

    const unsigned aQ  = smb + ((SQ  + (rb + t01*8 + li)*QW + t23*4) << 2);
    const unsigned aK0 = smb + ((SK0 + (t23*8 + li)*QW + t01*4) << 2);
    const unsigned aK1 = smb + ((SK1 + (t23*8 + li)*QW + t01*4) << 2);
    const unsigned aV0 = smb + ((SV0 + (t01*8 + li)*QW + t23*4) << 2);
    const unsigned aV1 = smb + ((SV1 + (t01*8 + li)*QW + t23*4) << 2);

    // per-thread cp.async slots for a KV tile (4 x 16B each for K and V)
    int cprow[4], cpcw[4];
#pragma unroll
    for (int u = 0; u < 4; u++) {
        int idx = tid + u*256;
        cprow[u] = idx >> 3;
        cpcw[u]  = (idx & 7) << 2;
    }

    // ---- issue K/V tile t into buffer bs ----
    auto issueKV = [&](int t, int bs) {
        const unsigned kb = smb + ((bs ? SK1 : SK0) << 2);
        const unsigned vb = smb + ((bs ? SV1 : SV0) << 2);
#pragma unroll
        for (int u = 0; u < 4; u++) {
            size_t gw = (size_t)(b*NT + t + cprow[u])*NDW + h*32 + cpcw[u];
            unsigned soff = (cprow[u]*QW + cpcw[u]) << 2;
            cpa16(kb + soff, g_Kb + gw);
            cpa16(vb + soff, g_Vb + gw);
        }
        cpa_commit();
    };

    issueKV(0, 0);

    // ---- Q tile fill (prescaled bf16, direct copy) ----
#pragma unroll
    for (int u = 0; u < 4; u++) {
        int idx = tid + u*256;
        int row = idx >> 3;
        int cw  = (idx & 7) << 2;
        uint4 x = *(const uint4*)(g_Qb + (size_t)(b*NT + q0 + row)*NDW + h*32 + cw);
        *(uint4*)(sm + SQ + row*QW + cw) = x;
    }
    __syncthreads();

    // Q fragments to registers (constant across kv loop)
    unsigned qa[4][4];
#pragma unroll
    for (int st = 0; st < 4; st++)
        ldm4(qa[st][0], qa[st][1], qa[st][2], qa[st][3], aQ + st*32);

    float m1 = -1e30f, m2 = -1e30f, l1 = 0.f, l2 = 0.f;
    float o[8][4];
#pragma unroll
    for (int j = 0; j < 8; j++)
#pragma unroll
        for (int i = 0; i < 4; i++) o[j][i] = 0.f;

    for (int t8 = 0; t8 < 8; t8++) {
        if (t8 < 7) { issueKV((t8+1)*128, (t8+1)&1); cpa_wait<1>(); }
        else        { cpa_wait<0>(); }
        __syncthreads();

        const unsigned aKc = (t8 & 1) ? aK1 : aK0;
        const unsigned aVc = (t8 & 1) ? aV1 : aV0;

        // ---- S = Q K^T ----
        float s[16][4];
#pragma unroll
        for (int j = 0; j < 16; j++)
#pragma unroll
            for (int i = 0; i < 4; i++) s[j][i] = 0.f;

#pragma unroll
        for (int st = 0; st < 4; st++) {
#pragma unroll
            for (int jp = 0; jp < 8; jp++) {
                unsigned b0,b1,b2,b3;
                ldm4(b0,b1,b2,b3, aKc + jp*(16*QW*4) + st*32);
                mma16(s[2*jp],   qa[st][0],qa[st][1],qa[st][2],qa[st][3], b0,b1);
                mma16(s[2*jp+1], qa[st][0],qa[st][1],qa[st][2],qa[st][3], b2,b3);
            }
        }

        // ---- + transport bias, row max ----
        const int t = t8 * 128;
        float mx1 = -1e30f, mx2 = -1e30f;
        const size_t base1 = (size_t)(b*NT + q0 + r1)*NT + t;
        const size_t base2 = (size_t)(b*NT + q0 + r2)*NT + t;
#pragma unroll
        for (int j = 0; j < 16; j++) {
            int col = j*8 + 2*tg;
            float2 g1 = *(const float2*)(bias + base1 + col);
            float2 g2 = *(const float2*)(bias + base2 + col);
            s[j][0] += g1.x;  s[j][1] += g1.y;
            s[j][2] += g2.x;  s[j][3] += g2.y;
            mx1 = fmaxf(mx1, fmaxf(s[j][0], s[j][1]));
            mx2 = fmaxf(mx2, fmaxf(s[j][2], s[j][3]));
        }
        mx1 = fmaxf(mx1, __shfl_xor_sync(0xffffffffu, mx1, 1));
        mx1 = fmaxf(mx1, __shfl_xor_sync(0xffffffffu, mx1, 2));
        mx2 = fmaxf(mx2, __shfl_xor_sync(0xffffffffu, mx2, 1));
        mx2 = fmaxf(mx2, __shfl_xor_sync(0xffffffffu, mx2, 2));

        float mn1 = fmaxf(m1, mx1), mn2 = fmaxf(m2, mx2);
        float corr1 = __expf(m1 - mn1), corr2 = __expf(m2 - mn2);
        m1 = mn1; m2 = mn2;

        // ---- exp + pack in place: s[j][0] <- pack(p0,p1), s[j][1] <- pack(p2,p3)
        float rs1 = 0.f, rs2 = 0.f;
#pragma unroll
        for (int j = 0; j < 16; j++) {
            float p0 = __expf(s[j][0] - m1);
            float p1 = __expf(s[j][1] - m1);
            float p2 = __expf(s[j][2] - m2);
            float p3 = __expf(s[j][3] - m2);
            rs1 += p0 + p1;  rs2 += p2 + p3;
            s[j][0] = __uint_as_float(pack_bf16(p0, p1));
            s[j][1] = __uint_as_float(pack_bf16(p2, p3));
        }
        rs1 += __shfl_xor_sync(0xffffffffu, rs1, 1);
        rs1 += __shfl_xor_sync(0xffffffffu, rs1, 2);
        rs2 += __shfl_xor_sync(0xffffffffu, rs2, 1);
        rs2 += __shfl_xor_sync(0xffffffffu, rs2, 2);
        l1 = l1*corr1 + rs1;
        l2 = l2*corr2 + rs2;
#pragma unroll
        for (int j = 0; j < 8; j++) {
            o[j][0] *= corr1; o[j][1] *= corr1;
            o[j][2] *= corr2; o[j][3] *= corr2;
        }

        // ---- acc += P @ V  (P fragments straight from registers) ----
#pragma unroll
        for (int st = 0; st < 8; st++) {
            unsigned a0 = __float_as_uint(s[2*st  ][0]);
            unsigned a1 = __float_as_uint(s[2*st  ][1]);
            unsigned a2 = __float_as_uint(s[2*st+1][0]);
            unsigned a3 = __float_as_uint(s[2*st+1][1]);
#pragma unroll
            for (int jp = 0; jp < 4; jp++) {
                unsigned b0,b1,b2,b3;
                ldm4t(b0,b1,b2,b3, aVc + st*(16*QW*4) + jp*32);
                mma16(o[2*jp],   a0,a1,a2,a3, b0,b1);
                mma16(o[2*jp+1], a0,a1,a2,a3, b2,b3);
            }
        }
        __syncthreads();                 // buffer free for iter t8+1's issue
    }

    // ---- normalize + write context (bf16x2 packed) ----
    float inv1 = 1.f / l1, inv2 = 1.f / l2;
#pragma unroll
    for (int j = 0; j < 8; j++) {
        int col = h*NHD + j*8 + 2*tg;
        g_ctxb[((size_t)(b*NT + q0 + r1)*ND + col) >> 1] =
            pack_bf16(o[j][0]*inv1, o[j][1]*inv1);
        g_ctxb[((size_t)(b*NT + q0 + r2)*ND + col) >> 1] =
            pack_bf16(o[j][2]*inv2, o[j][3]*inv2);
    }
}

// ===========================================================================
// Fused residual + gate + LayerNorm.  One 128-thread block per row.
// ===========================================================================
__global__ void __launch_bounds__(128,8)
k_ln(const float* __restrict__ qin, const float* __restrict__ gate,
     const float* __restrict__ gamma, const float* __restrict__ beta,
     float* __restrict__ out)
{
    const int row = blockIdx.x;
    const int t   = threadIdx.x;
    const int wid = t >> 5, lane = t & 31;
    const float sg = 1.f/(1.f + __expf(-gate[0]));

    float y[4];
    float s = 0.f;
#pragma unroll
    for (int u = 0; u < 4; u++) {
        int c = t + u*128;
        y[u] = qin[(size_t)row*ND + c] + sg * g_proj[(size_t)row*ND + c];
        s += y[u];
    }
    __shared__ float red1[4], red2[4];
#pragma unroll
    for (int off = 16; off >= 1; off >>= 1) s += __shfl_xor_sync(0xffffffffu, s, off);
    if (lane == 0) red1[wid] = s;
    __syncthreads();
    float mu = (red1[0]+red1[1]+red1[2]+red1[3]) * (1.f/ND);

    float vs = 0.f;
#pragma unroll
    for (int u = 0; u < 4; u++) { float d = y[u]-mu; vs += d*d; }
#pragma unroll
    for (int off = 16; off >= 1; off >>= 1) vs += __shfl_xor_sync(0xffffffffu, vs, off);
    if (lane == 0) red2[wid] = vs;
    __syncthreads();
    float var  = (red2[0]+red2[1]+red2[2]+red2[3]) * (1.f/ND);
    float rstd = rsqrtf(var + 1e-5f);

#pragma unroll
    for (int u = 0; u < 4; u++) {
        int c = t + u*128;
        out[(size_t)row*ND + c] = (y[u]-mu)*rstd*gamma[c] + beta[c];
    }
}

// ===========================================================================
extern "C" void kernel_launch(void* const* d_in, const int* in_sizes, int n_in,
                              void* d_out, int out_size)
{
    (void)in_sizes; (void)n_in; (void)out_size;
    const float* q          = (const float*)d_in[0];
    const float* k          = (const float*)d_in[1];
    const float* v          = (const float*)d_in[2];
    const float* guide      = (const float*)d_in[3];
    const float* Wq         = (const float*)d_in[4];
    const float* bq         = (const float*)d_in[5];
    const float* Wk         = (const float*)d_in[6];
    const float* bk         = (const float*)d_in[7];
    const float* Wv         = (const float*)d_in[8];
    const float* bv         = (const float*)d_in[9];
    const float* Wo         = (const float*)d_in[10];
    const float* bo         = (const float*)d_in[11];
    const float* ln_gamma   = (const float*)d_in[12];
    const float* ln_beta    = (const float*)d_in[13];
    const float* gate       = (const float*)d_in[14];
    const float* bias_scale = (const float*)d_in[15];
    float* out = (float*)d_out;

    cudaFuncSetAttribute(k_attn, cudaFuncAttributeMaxDynamicSharedMemorySize, SMEM_ATTN);

    // fused bias precompute (z=0) + Q/K/V projections (z=1..3)
    k_qkvb<<<dim3(8, 32, 4), 256>>>(q, k, v, Wq, bq, Wk, bk, Wv, bv,
                                    guide, bias_scale);
    // attention (h fastest for bias L2 reuse)
    k_attn<<<dim3(NH, NT/128, NB), 256, SMEM_ATTN>>>();
    // output projection
    k_oproj<<<dim3(8, 32), 256>>>(Wo, bo);
    // residual + gate + layernorm
    k_ln<<<NM, 128>>>(q, gate, ln_gamma, ln_beta, out);
}